// round 5
// baseline (speedup 1.0000x reference)
#include <cuda_runtime.h>
#include <cuda_bf16.h>
#include <math.h>

#define B_ 128
#define C_ 128
#define T_ 64
#define V_ 25
#define R_ 16
#define O_ 256
#define T2_ 32
#define COLS 800   // T2_*V_

// ---------------- scratch (device globals; no allocs allowed) ----------------
__device__ float g_sf[B_*C_*V_];          // mean over T   [b][c][v]
__device__ float g_tf[B_*C_*T_];          // mean over V   [b][c][t]
__device__ float g_As[B_*V_*V_];          // As = As_at + As_act
__device__ float g_Ate[B_*T_*T2_];        // At[:, ::2]  [b][t][y]
__device__ float g_nu2[B_*C_*COLS];       // after graph mix [b][c][y*25+v]
__device__ float g_x[B_*C_*COLS];         // after sp+bn

// ---------------- K1: fused means over T and V ----------------
__global__ void k_reduce(const float* __restrict__ g1) {
    int bc = blockIdx.x;                       // b*C + c
    const float* p = g1 + (size_t)bc * (T_*V_);
    __shared__ __align__(16) float s[T_*V_];
    for (int i = threadIdx.x; i < T_*V_; i += blockDim.x) s[i] = p[i];
    __syncthreads();
    int tid = threadIdx.x;
    if (tid < T_) {
        float acc = 0.f;
        #pragma unroll
        for (int v = 0; v < V_; v++) acc += s[tid*V_ + v];
        g_tf[(size_t)bc*T_ + tid] = acc * (1.f/V_);
    } else if (tid < T_ + V_) {
        int v = tid - T_;
        float acc = 0.f;
        #pragma unroll
        for (int t = 0; t < T_; t++) acc += s[t*V_ + v];
        g_sf[(size_t)bc*V_ + v] = acc * (1.f/T_);
    }
}

// ---------------- K2s: spatial attention branch (per batch) ----------------
__global__ void k_As(const float* __restrict__ sc1_w, const float* __restrict__ sc1_b,
                     const float* __restrict__ sc2_w, const float* __restrict__ sc2_b,
                     const float* __restrict__ As_r,  const float* __restrict__ act_s,
                     float* __restrict__ out_As_at,   float* __restrict__ out_As_act) {
    int b = blockIdx.x;
    __shared__ __align__(16) float sfs[C_*V_];          // [c][v]
    __shared__ __align__(16) float s1[V_][R_];
    __shared__ __align__(16) float s2[R_][V_ + 1];
    for (int i = threadIdx.x; i < C_*V_; i += blockDim.x)
        sfs[i] = g_sf[(size_t)b*C_*V_ + i];
    __syncthreads();
    for (int i = threadIdx.x; i < V_*R_; i += blockDim.x) {
        int v = i / R_, r = i % R_;
        float a1 = sc1_b[r], a2 = sc2_b[r];
        #pragma unroll 8
        for (int c = 0; c < C_; c++) {
            float f = sfs[c*V_ + v];
            a1 += sc1_w[r*C_ + c] * f;
            a2 += sc2_w[r*C_ + c] * f;
        }
        s1[v][r] = a1;
        s2[r][v] = a2;
    }
    __syncthreads();
    for (int i = threadIdx.x; i < V_*V_; i += blockDim.x) {
        int v = i / V_, u = i % V_;
        float a = 0.f;
        #pragma unroll
        for (int r = 0; r < R_; r++) a += s1[v][r] * s2[r][u];
        float at  = fmaxf(tanhf(a), 0.f);
        float act = As_r[(size_t)b*V_*V_ + i] * act_s[i];
        out_As_at[(size_t)b*V_*V_ + i]  = at;
        out_As_act[(size_t)b*V_*V_ + i] = act;
        g_As[(size_t)b*V_*V_ + i] = at + act;
    }
}

// ---------------- K2t: temporal attention branch (per batch) ----------------
__global__ void k_At(const float* __restrict__ tc1_w, const float* __restrict__ tc1_b,
                     const float* __restrict__ tc2_w, const float* __restrict__ tc2_b,
                     const float* __restrict__ At_r,  const float* __restrict__ act_t,
                     float* __restrict__ out_At_at,   float* __restrict__ out_At_act) {
    int b = blockIdx.x;
    __shared__ __align__(16) float tfs[C_*T_];          // [c][t]  32KB
    __shared__ __align__(16) float t1[T_][R_];
    __shared__ __align__(16) float t2[R_][T_];
    for (int i = threadIdx.x; i < C_*T_; i += blockDim.x)
        tfs[i] = g_tf[(size_t)b*C_*T_ + i];
    __syncthreads();
    for (int i = threadIdx.x; i < T_*R_; i += blockDim.x) {
        int t = i / R_, r = i % R_;
        float a1 = tc1_b[r], a2 = tc2_b[r];
        #pragma unroll 8
        for (int c = 0; c < C_; c++) {
            float f = tfs[c*T_ + t];
            a1 += tc1_w[r*C_ + c] * f;
            a2 += tc2_w[r*C_ + c] * f;
        }
        t1[t][r] = a1;
        t2[r][t] = a2;
    }
    __syncthreads();
    for (int i = threadIdx.x; i < T_*T_; i += blockDim.x) {
        int t = i / T_, y = i % T_;
        float a = 0.f;
        #pragma unroll
        for (int r = 0; r < R_; r++) a += t1[t][r] * t2[r][y];
        float at  = fmaxf(tanhf(a), 0.f);
        float act = At_r[(size_t)b*T_*T_ + i] * act_t[i];
        out_At_at[(size_t)b*T_*T_ + i]  = at;
        out_At_act[(size_t)b*T_*T_ + i] = act;
        if ((y & 1) == 0)
            g_Ate[(size_t)b*T_*T2_ + t*T2_ + (y >> 1)] = at + act;
    }
}

// ---------------- K3: fused graph mix: nu2[b,c,y,u] = sum_t At[t,2y] * sum_v As[u,v] g1[b,c,t,v]
__global__ void k_mix(const float* __restrict__ g1) {
    int bc = blockIdx.x;                // b*C + c
    int b = bc >> 7;
    __shared__ __align__(16) float g1s[T_*V_];        // 1600
    __shared__ __align__(16) float Ass[V_*V_];        // 625
    __shared__ __align__(16) float Ats[T_*T2_];       // 2048  [t][y] rows of 32
    __shared__ __align__(16) float Ms[T_*V_];         // 1600  [t][u]
    const float* p = g1 + (size_t)bc * (T_*V_);
    for (int i = threadIdx.x; i < T_*V_; i += blockDim.x) g1s[i] = p[i];
    for (int i = threadIdx.x; i < V_*V_; i += blockDim.x) Ass[i] = g_As[(size_t)b*V_*V_ + i];
    for (int i = threadIdx.x; i < T_*T2_; i += blockDim.x) Ats[i] = g_Ate[(size_t)b*T_*T2_ + i];
    __syncthreads();
    // stage 1: Ms[t][u] = sum_v g1s[t][v] * Ass[u][v]
    for (int i = threadIdx.x; i < T_*V_; i += blockDim.x) {
        int t = i / V_, u = i % V_;
        float a = 0.f;
        #pragma unroll
        for (int v = 0; v < V_; v++) a += g1s[t*V_ + v] * Ass[u*V_ + v];
        Ms[i] = a;
    }
    __syncthreads();
    // stage 2: out[y][u] = sum_t Ms[t][u] * Ats[t][y]; thread = (u, y-quad)
    int tid = threadIdx.x;
    if (tid < V_ * 8) {
        int u = tid % V_, y4 = tid / V_;
        float a0 = 0.f, a1 = 0.f, a2 = 0.f, a3 = 0.f;
        #pragma unroll 8
        for (int t = 0; t < T_; t++) {
            float m = Ms[t*V_ + u];
            float4 at = *(const float4*)&Ats[t*T2_ + y4*4];
            a0 += m * at.x; a1 += m * at.y; a2 += m * at.z; a3 += m * at.w;
        }
        float* o = g_nu2 + (size_t)bc * COLS + u;
        o[(y4*4 + 0)*V_] = a0;
        o[(y4*4 + 1)*V_] = a1;
        o[(y4*4 + 2)*V_] = a2;
        o[(y4*4 + 3)*V_] = a3;
    }
}

// ---------------- K4: sp GEMM + BN ----------------
#define TK 16
__global__ void k_sp(const float* __restrict__ sp_w, const float* __restrict__ sp_b,
                     const float* __restrict__ gm, const float* __restrict__ bt,
                     const float* __restrict__ mn, const float* __restrict__ vr) {
    int b  = blockIdx.z;
    int o0 = blockIdx.y * 64;
    int c0 = blockIdx.x * 64;
    __shared__ __align__(16) float Wt[64][TK];        // [oo][kk]
    __shared__ __align__(16) float Xt[TK][64];        // [kk][cc]
    int tid = threadIdx.x;
    int tx = tid & 15, ty = tid >> 4;
    float acc[4][4] = {};
    const float* Xb = g_nu2 + (size_t)b * C_ * COLS;
    for (int k0 = 0; k0 < C_; k0 += TK) {
        for (int i = tid; i < 64*TK; i += 256) {
            int kk = i % TK, oo = i / TK;
            Wt[oo][kk] = sp_w[(o0 + oo)*C_ + k0 + kk];
        }
        for (int i = tid; i < TK*64; i += 256) {
            int cc = i % 64, kk = i / 64;
            int col = c0 + cc;
            Xt[kk][cc] = (col < COLS) ? Xb[(size_t)(k0 + kk)*COLS + col] : 0.f;
        }
        __syncthreads();
        #pragma unroll
        for (int k = 0; k < TK; k++) {
            float4 xb = *(const float4*)&Xt[k][tx*4];
            float w[4];
            #pragma unroll
            for (int i = 0; i < 4; i++) w[i] = Wt[ty*4 + i][k];
            #pragma unroll
            for (int i = 0; i < 4; i++) {
                acc[i][0] += w[i]*xb.x; acc[i][1] += w[i]*xb.y;
                acc[i][2] += w[i]*xb.z; acc[i][3] += w[i]*xb.w;
            }
        }
        __syncthreads();
    }
    #pragma unroll
    for (int i = 0; i < 4; i++) {
        int o = o0 + ty*4 + i;
        float sc = gm[o] * rsqrtf(vr[o] + 1e-5f);
        float bb = bt[o] - mn[o]*sc;
        float bias = sp_b[o];
        #pragma unroll
        for (int j = 0; j < 4; j++) {
            int col = c0 + tx*4 + j;
            if (col < COLS)
                g_x[((size_t)b*C_ + o)*COLS + col] = (acc[i][j] + bias)*sc + bb;
        }
    }
}

// ---------------- K5: fused W1/W2 GEMM + gate + BN -> g2 ----------------
__global__ void k_out(const float* __restrict__ h2,
                      const float* __restrict__ W1_w, const float* __restrict__ W1_b,
                      const float* __restrict__ W2_w, const float* __restrict__ W2_b,
                      const float* __restrict__ gm, const float* __restrict__ bt,
                      const float* __restrict__ mn, const float* __restrict__ vr,
                      float* __restrict__ g2) {
    int b  = blockIdx.z;
    int o0 = blockIdx.y * 64;
    int c0 = blockIdx.x * 64;
    __shared__ __align__(16) float W1t[64][TK];
    __shared__ __align__(16) float W2t[64][TK];
    __shared__ __align__(16) float Xt[TK][64];
    int tid = threadIdx.x;
    int tx = tid & 15, ty = tid >> 4;
    float accA[4][4] = {};
    float accG[4][4] = {};
    for (int k0 = 0; k0 < 2*C_; k0 += TK) {
        for (int i = tid; i < 64*TK; i += 256) {
            int kk = i % TK, oo = i / TK;
            W1t[oo][kk] = W1_w[(o0 + oo)*(2*C_) + k0 + kk];
            W2t[oo][kk] = W2_w[(o0 + oo)*(2*C_) + k0 + kk];
        }
        const float* src = (k0 < C_) ? (g_x + (size_t)(b*C_ + k0)*COLS)
                                     : (h2  + (size_t)(b*C_ + (k0 - C_))*COLS);
        for (int i = tid; i < TK*64; i += 256) {
            int cc = i % 64, kk = i / 64;
            int col = c0 + cc;
            Xt[kk][cc] = (col < COLS) ? src[(size_t)kk*COLS + col] : 0.f;
        }
        __syncthreads();
        #pragma unroll
        for (int k = 0; k < TK; k++) {
            float4 xb = *(const float4*)&Xt[k][tx*4];
            float w1[4], w2[4];
            #pragma unroll
            for (int i = 0; i < 4; i++) { w1[i] = W1t[ty*4 + i][k]; w2[i] = W2t[ty*4 + i][k]; }
            #pragma unroll
            for (int i = 0; i < 4; i++) {
                accA[i][0] += w1[i]*xb.x; accA[i][1] += w1[i]*xb.y;
                accA[i][2] += w1[i]*xb.z; accA[i][3] += w1[i]*xb.w;
                accG[i][0] += w2[i]*xb.x; accG[i][1] += w2[i]*xb.y;
                accG[i][2] += w2[i]*xb.z; accG[i][3] += w2[i]*xb.w;
            }
        }
        __syncthreads();
    }
    #pragma unroll
    for (int i = 0; i < 4; i++) {
        int o = o0 + ty*4 + i;
        float sc = gm[o] * rsqrtf(vr[o] + 1e-5f);
        float bb = bt[o] - mn[o]*sc;
        float b1 = W1_b[o], b2 = W2_b[o];
        #pragma unroll
        for (int j = 0; j < 4; j++) {
            int col = c0 + tx*4 + j;
            if (col < COLS) {
                float a = accA[i][j] + b1;
                float g = accG[i][j] + b2;
                float v = a * (1.f / (1.f + expf(-g)));
                g2[((size_t)b*O_ + o)*COLS + col] = v*sc + bb;
            }
        }
    }
}

// ---------------- launch ----------------
extern "C" void kernel_launch(void* const* d_in, const int* in_sizes, int n_in,
                              void* d_out, int out_size) {
    const float* g1    = (const float*)d_in[0];
    const float* h2    = (const float*)d_in[1];
    const float* As_r  = (const float*)d_in[2];
    const float* At_r  = (const float*)d_in[3];
    const float* sc1_w = (const float*)d_in[4];
    const float* sc1_b = (const float*)d_in[5];
    const float* sc2_w = (const float*)d_in[6];
    const float* sc2_b = (const float*)d_in[7];
    const float* tc1_w = (const float*)d_in[8];
    const float* tc1_b = (const float*)d_in[9];
    const float* tc2_w = (const float*)d_in[10];
    const float* tc2_b = (const float*)d_in[11];
    const float* act_s = (const float*)d_in[12];
    const float* act_t = (const float*)d_in[13];
    const float* sp_w  = (const float*)d_in[14];
    const float* sp_b  = (const float*)d_in[15];
    const float* sp_gm = (const float*)d_in[16];
    const float* sp_bt = (const float*)d_in[17];
    const float* sp_mn = (const float*)d_in[18];
    const float* sp_vr = (const float*)d_in[19];
    const float* W1_w  = (const float*)d_in[20];
    const float* W1_b  = (const float*)d_in[21];
    const float* W2_w  = (const float*)d_in[22];
    const float* W2_b  = (const float*)d_in[23];
    const float* bn_gm = (const float*)d_in[24];
    const float* bn_bt = (const float*)d_in[25];
    const float* bn_mn = (const float*)d_in[26];
    const float* bn_vr = (const float*)d_in[27];

    float* out = (float*)d_out;
    float* out_g2     = out;                       // 26,214,400
    float* out_As_at  = out + 26214400;            // 80,000
    float* out_At_at  = out + 26294400;            // 524,288
    float* out_As_act = out + 26818688;            // 80,000
    float* out_At_act = out + 26898688;            // 524,288

    k_reduce<<<B_*C_, 256>>>(g1);
    k_As<<<B_, 256>>>(sc1_w, sc1_b, sc2_w, sc2_b, As_r, act_s, out_As_at, out_As_act);
    k_At<<<B_, 256>>>(tc1_w, tc1_b, tc2_w, tc2_b, At_r, act_t, out_At_at, out_At_act);
    k_mix<<<B_*C_, 256>>>(g1);
    k_sp<<<dim3(13, 2, B_), 256>>>(sp_w, sp_b, sp_gm, sp_bt, sp_mn, sp_vr);
    k_out<<<dim3(13, 4, B_), 256>>>(h2, W1_w, W1_b, W2_w, W2_b,
                                    bn_gm, bn_bt, bn_mn, bn_vr, out_g2);
}

// round 7
// speedup vs baseline: 1.5121x; 1.5121x over previous
#include <cuda_runtime.h>
#include <cuda_bf16.h>
#include <math.h>

#define B_ 128
#define C_ 128
#define T_ 64
#define V_ 25
#define R_ 16
#define O_ 256
#define T2_ 32
#define COLS 800   // T2_*V_

typedef unsigned long long ull;

__device__ __forceinline__ ull pack2(float x) {
    ull r; asm("mov.b64 %0, {%1, %1};" : "=l"(r) : "f"(x)); return r;
}
__device__ __forceinline__ void fma2(ull &d, ull a, ull b) {
    asm("fma.rn.f32x2 %0, %1, %2, %0;" : "+l"(d) : "l"(a), "l"(b));
}
__device__ __forceinline__ float2 unpack2(ull a) {
    float2 f; asm("mov.b64 {%0, %1}, %2;" : "=f"(f.x), "=f"(f.y) : "l"(a)); return f;
}

// ---------------- scratch (device globals; no allocs allowed) ----------------
__device__ float g_sf[B_*C_*V_];          // mean over T   [b][c][v]
__device__ float g_tf[B_*C_*T_];          // mean over V   [b][c][t]
__device__ float g_As[B_*V_*V_];          // As = As_at + As_act
__device__ float g_Ate[B_*T_*T2_];        // At[:, ::2]  [b][t][y]
__device__ float g_nu2[B_*C_*COLS];       // after graph mix [b][c][y*25+v]
__device__ float g_W1e[O_*C_];            // W1[:, :C] @ (diag(sc_sp) @ sp_w)
__device__ float g_W2e[O_*C_];
__device__ float g_b1e[O_];               // W1_b + W1[:, :C] @ d_sp
__device__ float g_b2e[O_];

// ---------------- K1: fused means over T and V ----------------
__global__ void k_reduce(const float* __restrict__ g1) {
    int bc = blockIdx.x;                       // b*C + c
    const float* p = g1 + (size_t)bc * (T_*V_);
    __shared__ __align__(16) float s[T_*V_];
    for (int i = threadIdx.x; i < T_*V_; i += blockDim.x) s[i] = p[i];
    __syncthreads();
    int tid = threadIdx.x;
    if (tid < T_) {
        float acc = 0.f;
        #pragma unroll
        for (int v = 0; v < V_; v++) acc += s[tid*V_ + v];
        g_tf[(size_t)bc*T_ + tid] = acc * (1.f/V_);
    } else if (tid < T_ + V_) {
        int v = tid - T_;
        float acc = 0.f;
        #pragma unroll
        for (int t = 0; t < T_; t++) acc += s[t*V_ + v];
        g_sf[(size_t)bc*V_ + v] = acc * (1.f/T_);
    }
}

// ---------------- K2s: spatial attention branch (per batch) ----------------
__global__ void k_As(const float* __restrict__ sc1_w, const float* __restrict__ sc1_b,
                     const float* __restrict__ sc2_w, const float* __restrict__ sc2_b,
                     const float* __restrict__ As_r,  const float* __restrict__ act_s,
                     float* __restrict__ out_As_at,   float* __restrict__ out_As_act) {
    int b = blockIdx.x;
    __shared__ __align__(16) float sfs[C_*V_];          // [c][v]
    __shared__ __align__(16) float s1[V_][R_];
    __shared__ __align__(16) float s2[R_][V_ + 1];
    for (int i = threadIdx.x; i < C_*V_; i += blockDim.x)
        sfs[i] = g_sf[(size_t)b*C_*V_ + i];
    __syncthreads();
    for (int i = threadIdx.x; i < V_*R_; i += blockDim.x) {
        int v = i / R_, r = i % R_;
        float a1 = sc1_b[r], a2 = sc2_b[r];
        #pragma unroll 8
        for (int c = 0; c < C_; c++) {
            float f = sfs[c*V_ + v];
            a1 += sc1_w[r*C_ + c] * f;
            a2 += sc2_w[r*C_ + c] * f;
        }
        s1[v][r] = a1;
        s2[r][v] = a2;
    }
    __syncthreads();
    for (int i = threadIdx.x; i < V_*V_; i += blockDim.x) {
        int v = i / V_, u = i % V_;
        float a = 0.f;
        #pragma unroll
        for (int r = 0; r < R_; r++) a += s1[v][r] * s2[r][u];
        float at  = fmaxf(tanhf(a), 0.f);
        float act = As_r[(size_t)b*V_*V_ + i] * act_s[i];
        out_As_at[(size_t)b*V_*V_ + i]  = at;
        out_As_act[(size_t)b*V_*V_ + i] = act;
        g_As[(size_t)b*V_*V_ + i] = at + act;
    }
}

// ---------------- K2t: temporal attention branch (per batch) ----------------
__global__ void k_At(const float* __restrict__ tc1_w, const float* __restrict__ tc1_b,
                     const float* __restrict__ tc2_w, const float* __restrict__ tc2_b,
                     const float* __restrict__ At_r,  const float* __restrict__ act_t,
                     float* __restrict__ out_At_at,   float* __restrict__ out_At_act) {
    int b = blockIdx.x;
    __shared__ __align__(16) float tfs[C_*T_];          // [c][t]  32KB
    __shared__ __align__(16) float t1[T_][R_];
    __shared__ __align__(16) float t2[R_][T_];
    for (int i = threadIdx.x; i < C_*T_; i += blockDim.x)
        tfs[i] = g_tf[(size_t)b*C_*T_ + i];
    __syncthreads();
    for (int i = threadIdx.x; i < T_*R_; i += blockDim.x) {
        int t = i / R_, r = i % R_;
        float a1 = tc1_b[r], a2 = tc2_b[r];
        #pragma unroll 8
        for (int c = 0; c < C_; c++) {
            float f = tfs[c*T_ + t];
            a1 += tc1_w[r*C_ + c] * f;
            a2 += tc2_w[r*C_ + c] * f;
        }
        t1[t][r] = a1;
        t2[r][t] = a2;
    }
    __syncthreads();
    for (int i = threadIdx.x; i < T_*T_; i += blockDim.x) {
        int t = i / T_, y = i % T_;
        float a = 0.f;
        #pragma unroll
        for (int r = 0; r < R_; r++) a += t1[t][r] * t2[r][y];
        float at  = fmaxf(tanhf(a), 0.f);
        float act = At_r[(size_t)b*T_*T_ + i] * act_t[i];
        out_At_at[(size_t)b*T_*T_ + i]  = at;
        out_At_act[(size_t)b*T_*T_ + i] = act;
        if ((y & 1) == 0)
            g_Ate[(size_t)b*T_*T2_ + t*T2_ + (y >> 1)] = at + act;
    }
}

// ---------------- K_prep: fold sp-GEMM + BN into W1/W2 ----------------
// x = S*nu2 + d,  S[c][cc] = sc_sp[c]*sp_w[c][cc],  d[c] = sc_sp[c]*sp_b[c]+bb_sp[c]
// W1eff = W1[:, :C] @ S ; b1eff = W1_b + W1[:, :C] @ d
__global__ void k_prep(const float* __restrict__ sp_w, const float* __restrict__ sp_b,
                       const float* __restrict__ gm, const float* __restrict__ bt,
                       const float* __restrict__ mn, const float* __restrict__ vr,
                       const float* __restrict__ W1_w, const float* __restrict__ W1_b,
                       const float* __restrict__ W2_w, const float* __restrict__ W2_b) {
    int o = blockIdx.x;
    int t = threadIdx.x;   // 128
    __shared__ float w1r[C_], w2r[C_], ssh[C_], dsh[C_];
    float scc = gm[t] * rsqrtf(vr[t] + 1e-5f);
    float bb  = bt[t] - mn[t] * scc;
    ssh[t] = scc;
    dsh[t] = scc * sp_b[t] + bb;
    w1r[t] = W1_w[o*(2*C_) + t];
    w2r[t] = W2_w[o*(2*C_) + t];
    __syncthreads();
    float a1 = 0.f, a2 = 0.f;
    #pragma unroll 8
    for (int c = 0; c < C_; c++) {
        float spv = ssh[c] * sp_w[c*C_ + t];
        a1 += w1r[c] * spv;
        a2 += w2r[c] * spv;
    }
    g_W1e[o*C_ + t] = a1;
    g_W2e[o*C_ + t] = a2;
    if (t == 0) {
        float s1 = 0.f, s2 = 0.f;
        for (int c = 0; c < C_; c++) { s1 += w1r[c]*dsh[c]; s2 += w2r[c]*dsh[c]; }
        g_b1e[o] = W1_b[o] + s1;
        g_b2e[o] = W2_b[o] + s2;
    }
}

// ---------------- K3: fused graph mix (float4-vectorized, padded rows) ----------
__global__ void k_mix(const float* __restrict__ g1) {
    int bc = blockIdx.x;                // b*C + c
    int b = bc >> 7;
    __shared__ __align__(16) float g1p[T_][28];       // padded rows
    __shared__ __align__(16) float Asp[V_][28];
    __shared__ __align__(16) float Ats[T_*T2_];       // [t][y] rows of 32
    __shared__ __align__(16) float Ms[T_][28];        // [t][u]
    const float* p = g1 + (size_t)bc * (T_*V_);
    int tid = threadIdx.x;
    for (int i = tid; i < T_*28; i += 256) {
        int t = i / 28, v = i % 28;
        g1p[t][v] = (v < V_) ? p[t*V_ + v] : 0.f;
    }
    for (int i = tid; i < V_*28; i += 256) {
        int u = i / 28, v = i % 28;
        Asp[u][v] = (v < V_) ? g_As[(size_t)b*V_*V_ + u*V_ + v] : 0.f;
    }
    for (int i = tid; i < T_*T2_; i += 256) Ats[i] = g_Ate[(size_t)b*T_*T2_ + i];
    __syncthreads();
    // stage 1: Ms[t][u] = sum_v g1p[t][v] * Asp[u][v]   (7 float4 pairs)
    for (int i = tid; i < T_*V_; i += 256) {
        int t = i / V_, u = i % V_;
        float ax = 0.f, ay = 0.f, az = 0.f, aw = 0.f;
        #pragma unroll
        for (int g = 0; g < 7; g++) {
            float4 x = *(const float4*)&g1p[t][g*4];
            float4 y = *(const float4*)&Asp[u][g*4];
            ax += x.x*y.x; ay += x.y*y.y; az += x.z*y.z; aw += x.w*y.w;
        }
        Ms[t][u] = (ax + ay) + (az + aw);
    }
    __syncthreads();
    // stage 2: out[y][u] = sum_t Ms[t][u] * Ats[t][y]
    if (tid < V_ * 8) {
        int u = tid % V_, y4 = tid / V_;
        float a0 = 0.f, a1 = 0.f, a2 = 0.f, a3 = 0.f;
        #pragma unroll 8
        for (int t = 0; t < T_; t++) {
            float m = Ms[t][u];
            float4 at = *(const float4*)&Ats[t*T2_ + y4*4];
            a0 += m * at.x; a1 += m * at.y; a2 += m * at.z; a3 += m * at.w;
        }
        float* o = g_nu2 + (size_t)bc * COLS + u;
        o[(y4*4 + 0)*V_] = a0;
        o[(y4*4 + 1)*V_] = a1;
        o[(y4*4 + 2)*V_] = a2;
        o[(y4*4 + 3)*V_] = a3;
    }
}

// ---------------- K5: fused W1/W2 GEMM + gate + BN -> g2 (packed f32x2) -------
#define TKO 16
#define WPAD 132   // 128 + 4 pad (keeps 16B alignment, breaks 16-way STS conflict)
__global__ __launch_bounds__(256) void k_out(
                      const float* __restrict__ h2,
                      const float* __restrict__ W1_w, const float* __restrict__ W2_w,
                      const float* __restrict__ gm, const float* __restrict__ bt,
                      const float* __restrict__ mn, const float* __restrict__ vr,
                      float* __restrict__ g2) {
    int b  = blockIdx.z;
    int o0 = blockIdx.y * 128;
    int c0 = blockIdx.x * 64;
    __shared__ __align__(16) float W1t[TKO][WPAD];   // [kk][oo]
    __shared__ __align__(16) float W2t[TKO][WPAD];
    __shared__ __align__(16) float Xt[TKO][64];      // [kk][cc]
    int tid = threadIdx.x;
    int tx = tid & 15;          // 16 col-groups of 4
    int ty = tid >> 4;          // 16 row-groups of 8
    ull accA[4][4] = {};        // [o-pair][j]
    ull accG[4][4] = {};

    #pragma unroll 1
    for (int half = 0; half < 2; half++) {
        const float* w1src; const float* w2src; int wstride;
        const float* xsrc;
        if (half == 0) {
            w1src = g_W1e + (size_t)o0 * C_;
            w2src = g_W2e + (size_t)o0 * C_;
            wstride = C_;
            xsrc = g_nu2 + (size_t)b * C_ * COLS;
        } else {
            w1src = W1_w + (size_t)o0 * (2*C_) + C_;
            w2src = W2_w + (size_t)o0 * (2*C_) + C_;
            wstride = 2*C_;
            xsrc = h2 + (size_t)b * C_ * COLS;
        }
        #pragma unroll 1
        for (int k0 = 0; k0 < C_; k0 += TKO) {
            for (int i = tid; i < 128*TKO; i += 256) {
                int oo = i >> 4, kk = i & 15;
                W1t[kk][oo] = w1src[(size_t)oo * wstride + k0 + kk];
                W2t[kk][oo] = w2src[(size_t)oo * wstride + k0 + kk];
            }
            for (int i = tid; i < TKO*64; i += 256) {
                int kk = i >> 6, cc = i & 63;
                int col = c0 + cc;
                Xt[kk][cc] = (col < COLS) ? xsrc[(size_t)(k0 + kk)*COLS + col] : 0.f;
            }
            __syncthreads();
            #pragma unroll
            for (int k = 0; k < TKO; k++) {
                float4 xb = *(const float4*)&Xt[k][tx*4];
                ull xp0 = pack2(xb.x), xp1 = pack2(xb.y), xp2 = pack2(xb.z), xp3 = pack2(xb.w);
                ulonglong2 wa01 = *(const ulonglong2*)&W1t[k][ty*8];
                ulonglong2 wa23 = *(const ulonglong2*)&W1t[k][ty*8 + 4];
                ulonglong2 wg01 = *(const ulonglong2*)&W2t[k][ty*8];
                ulonglong2 wg23 = *(const ulonglong2*)&W2t[k][ty*8 + 4];
                ull wa[4] = {wa01.x, wa01.y, wa23.x, wa23.y};
                ull wg[4] = {wg01.x, wg01.y, wg23.x, wg23.y};
                #pragma unroll
                for (int ip = 0; ip < 4; ip++) {
                    fma2(accA[ip][0], wa[ip], xp0);
                    fma2(accA[ip][1], wa[ip], xp1);
                    fma2(accA[ip][2], wa[ip], xp2);
                    fma2(accA[ip][3], wa[ip], xp3);
                    fma2(accG[ip][0], wg[ip], xp0);
                    fma2(accG[ip][1], wg[ip], xp1);
                    fma2(accG[ip][2], wg[ip], xp2);
                    fma2(accG[ip][3], wg[ip], xp3);
                }
            }
            __syncthreads();
        }
    }

    int col = c0 + tx*4;
    if (col < COLS) {
        #pragma unroll
        for (int ip = 0; ip < 4; ip++) {
            float2 fa[4], fg[4];
            #pragma unroll
            for (int j = 0; j < 4; j++) { fa[j] = unpack2(accA[ip][j]); fg[j] = unpack2(accG[ip][j]); }
            #pragma unroll
            for (int h = 0; h < 2; h++) {
                int o = o0 + ty*8 + ip*2 + h;
                float sc = gm[o] * rsqrtf(vr[o] + 1e-5f);
                float bb = bt[o] - mn[o]*sc;
                float b1 = g_b1e[o], b2 = g_b2e[o];
                float4 vv;
                #pragma unroll
                for (int j = 0; j < 4; j++) {
                    float a = (h ? fa[j].y : fa[j].x) + b1;
                    float g = (h ? fg[j].y : fg[j].x) + b2;
                    float v = a / (1.f + __expf(-g));
                    ((float*)&vv)[j] = v*sc + bb;
                }
                *(float4*)&g2[((size_t)(b*O_ + o))*COLS + col] = vv;
            }
        }
    }
}

// ---------------- launch ----------------
extern "C" void kernel_launch(void* const* d_in, const int* in_sizes, int n_in,
                              void* d_out, int out_size) {
    const float* g1    = (const float*)d_in[0];
    const float* h2    = (const float*)d_in[1];
    const float* As_r  = (const float*)d_in[2];
    const float* At_r  = (const float*)d_in[3];
    const float* sc1_w = (const float*)d_in[4];
    const float* sc1_b = (const float*)d_in[5];
    const float* sc2_w = (const float*)d_in[6];
    const float* sc2_b = (const float*)d_in[7];
    const float* tc1_w = (const float*)d_in[8];
    const float* tc1_b = (const float*)d_in[9];
    const float* tc2_w = (const float*)d_in[10];
    const float* tc2_b = (const float*)d_in[11];
    const float* act_s = (const float*)d_in[12];
    const float* act_t = (const float*)d_in[13];
    const float* sp_w  = (const float*)d_in[14];
    const float* sp_b  = (const float*)d_in[15];
    const float* sp_gm = (const float*)d_in[16];
    const float* sp_bt = (const float*)d_in[17];
    const float* sp_mn = (const float*)d_in[18];
    const float* sp_vr = (const float*)d_in[19];
    const float* W1_w  = (const float*)d_in[20];
    const float* W1_b  = (const float*)d_in[21];
    const float* W2_w  = (const float*)d_in[22];
    const float* W2_b  = (const float*)d_in[23];
    const float* bn_gm = (const float*)d_in[24];
    const float* bn_bt = (const float*)d_in[25];
    const float* bn_mn = (const float*)d_in[26];
    const float* bn_vr = (const float*)d_in[27];

    float* out = (float*)d_out;
    float* out_g2     = out;                       // 26,214,400
    float* out_As_at  = out + 26214400;            // 80,000
    float* out_At_at  = out + 26294400;            // 524,288
    float* out_As_act = out + 26818688;            // 80,000
    float* out_At_act = out + 26898688;            // 524,288

    k_reduce<<<B_*C_, 256>>>(g1);
    k_prep<<<O_, 128>>>(sp_w, sp_b, sp_gm, sp_bt, sp_mn, sp_vr,
                        W1_w, W1_b, W2_w, W2_b);
    k_As<<<B_, 256>>>(sc1_w, sc1_b, sc2_w, sc2_b, As_r, act_s, out_As_at, out_As_act);
    k_At<<<B_, 256>>>(tc1_w, tc1_b, tc2_w, tc2_b, At_r, act_t, out_At_at, out_At_act);
    k_mix<<<B_*C_, 256>>>(g1);
    k_out<<<dim3(13, 2, B_), 256>>>(h2, W1_w, W2_w,
                                    bn_gm, bn_bt, bn_mn, bn_vr, out_g2);
}

// round 9
// speedup vs baseline: 2.3761x; 1.5713x over previous
#include <cuda_runtime.h>
#include <cuda_bf16.h>
#include <math.h>

#define B_ 128
#define C_ 128
#define T_ 64
#define V_ 25
#define R_ 16
#define O_ 256
#define T2_ 32
#define COLS 800   // T2_*V_

// ---------------- scratch (device globals; no allocs allowed) ----------------
__device__ float g_sf[B_*V_*C_];          // mean over T   [b][v][c]  (transposed)
__device__ float g_tf[B_*T_*C_];          // mean over V   [b][t][c]  (transposed)
__device__ float g_As[B_*V_*V_];          // As = As_at + As_act
__device__ float g_Ate[B_*T_*T2_];        // At[:, ::2]  [b][t][y]
__device__ float g_nu2[B_*C_*COLS];       // after graph mix [b][c][y*25+v]
__device__ float g_W1e[O_*C_];            // W1[:, :C] @ (diag(sc_sp) @ sp_w)
__device__ float g_W2e[O_*C_];
__device__ float g_b1e[O_];               // W1_b + W1[:, :C] @ d_sp
__device__ float g_b2e[O_];

__device__ __forceinline__ unsigned f2tf32(float f) {
    unsigned r; asm("cvt.rna.tf32.f32 %0, %1;" : "=r"(r) : "f"(f)); return r;
}
__device__ __forceinline__ void mma8(float* d, const unsigned* a, const unsigned* b) {
    asm volatile(
      "mma.sync.aligned.m16n8k8.row.col.f32.tf32.tf32.f32 "
      "{%0,%1,%2,%3},{%4,%5,%6,%7},{%8,%9},{%0,%1,%2,%3};\n"
      : "+f"(d[0]), "+f"(d[1]), "+f"(d[2]), "+f"(d[3])
      : "r"(a[0]), "r"(a[1]), "r"(a[2]), "r"(a[3]), "r"(b[0]), "r"(b[1]));
}

// ---------------- K1: fused means over T and V (transposed outputs) ----------
__global__ void k_reduce(const float* __restrict__ g1) {
    int bc = blockIdx.x;                       // b*C + c
    int b = bc >> 7, c = bc & 127;
    const float* p = g1 + (size_t)bc * (T_*V_);
    __shared__ __align__(16) float s[T_*V_];
    for (int i = threadIdx.x; i < T_*V_; i += blockDim.x) s[i] = p[i];
    __syncthreads();
    int tid = threadIdx.x;
    if (tid < T_) {
        float acc = 0.f;
        #pragma unroll
        for (int v = 0; v < V_; v++) acc += s[tid*V_ + v];
        g_tf[((size_t)b*T_ + tid)*C_ + c] = acc * (1.f/V_);
    } else if (tid < T_ + V_) {
        int v = tid - T_;
        float acc = 0.f;
        #pragma unroll
        for (int t = 0; t < T_; t++) acc += s[t*V_ + v];
        g_sf[((size_t)b*V_ + v)*C_ + c] = acc * (1.f/T_);
    }
}

// ---------------- K2s: spatial attention branch (per batch) ----------------
__global__ void k_As(const float* __restrict__ sc1_w, const float* __restrict__ sc1_b,
                     const float* __restrict__ sc2_w, const float* __restrict__ sc2_b,
                     const float* __restrict__ As_r,  const float* __restrict__ act_s,
                     float* __restrict__ out_As_at,   float* __restrict__ out_As_act) {
    int b = blockIdx.x;
    __shared__ __align__(16) float sfs[V_][132];
    __shared__ __align__(16) float s1[V_][R_];
    __shared__ __align__(16) float s2[R_][V_ + 3];
    int tid = threadIdx.x;
    for (int i = tid; i < V_*C_; i += 256) {
        int v = i >> 7, c = i & 127;
        sfs[v][c] = g_sf[((size_t)b*V_ + v)*C_ + c];
    }
    __syncthreads();
    for (int i = tid; i < V_*R_; i += 256) {
        int v = i / R_, r = i % R_;
        const float4* w1 = (const float4*)(sc1_w + r*C_);
        const float4* w2 = (const float4*)(sc2_w + r*C_);
        float a1 = 0.f, a2 = 0.f;
        #pragma unroll 8
        for (int g = 0; g < 32; g++) {
            float4 f = *(const float4*)&sfs[v][g*4];
            float4 x = w1[g], y = w2[g];
            a1 += x.x*f.x + x.y*f.y + x.z*f.z + x.w*f.w;
            a2 += y.x*f.x + y.y*f.y + y.z*f.z + y.w*f.w;
        }
        s1[v][r] = a1 + sc1_b[r];
        s2[r][v] = a2 + sc2_b[r];
    }
    __syncthreads();
    for (int i = tid; i < V_*V_; i += 256) {
        int v = i / V_, u = i % V_;
        float a = 0.f;
        #pragma unroll
        for (int r = 0; r < R_; r++) a += s1[v][r] * s2[r][u];
        float at  = fmaxf(tanhf(a), 0.f);
        float act = As_r[(size_t)b*V_*V_ + i] * act_s[i];
        out_As_at[(size_t)b*V_*V_ + i]  = at;
        out_As_act[(size_t)b*V_*V_ + i] = act;
        g_As[(size_t)b*V_*V_ + i] = at + act;
    }
}

// ---------------- K2t: temporal attention branch (per batch) ----------------
__global__ void k_At(const float* __restrict__ tc1_w, const float* __restrict__ tc1_b,
                     const float* __restrict__ tc2_w, const float* __restrict__ tc2_b,
                     const float* __restrict__ At_r,  const float* __restrict__ act_t,
                     float* __restrict__ out_At_at,   float* __restrict__ out_At_act) {
    int b = blockIdx.x;
    __shared__ __align__(16) float tft[T_][132];      // 33.8KB
    __shared__ __align__(16) float t1[T_][R_ + 1];
    __shared__ __align__(16) float t2[R_][T_ + 3];
    int tid = threadIdx.x;
    for (int i = tid; i < T_*C_; i += 256) {
        int t = i >> 7, c = i & 127;
        tft[t][c] = g_tf[((size_t)b*T_ + t)*C_ + c];
    }
    __syncthreads();
    for (int i = tid; i < T_*R_; i += 256) {
        int t = i / R_, r = i % R_;
        const float4* w1 = (const float4*)(tc1_w + r*C_);
        const float4* w2 = (const float4*)(tc2_w + r*C_);
        float a1 = 0.f, a2 = 0.f;
        #pragma unroll 8
        for (int g = 0; g < 32; g++) {
            float4 f = *(const float4*)&tft[t][g*4];
            float4 x = w1[g], y = w2[g];
            a1 += x.x*f.x + x.y*f.y + x.z*f.z + x.w*f.w;
            a2 += y.x*f.x + y.y*f.y + y.z*f.z + y.w*f.w;
        }
        t1[t][r] = a1 + tc1_b[r];
        t2[r][t] = a2 + tc2_b[r];
    }
    __syncthreads();
    for (int i = tid; i < T_*T_; i += 256) {
        int t = i / T_, y = i % T_;
        float a = 0.f;
        #pragma unroll
        for (int r = 0; r < R_; r++) a += t1[t][r] * t2[r][y];
        float at  = fmaxf(tanhf(a), 0.f);
        float act = At_r[(size_t)b*T_*T_ + i] * act_t[i];
        out_At_at[(size_t)b*T_*T_ + i]  = at;
        out_At_act[(size_t)b*T_*T_ + i] = act;
        if ((y & 1) == 0)
            g_Ate[(size_t)b*T_*T2_ + t*T2_ + (y >> 1)] = at + act;
    }
}

// ---------------- K_prep: fold sp-GEMM + BN into W1/W2 ----------------
__global__ void k_prep(const float* __restrict__ sp_w, const float* __restrict__ sp_b,
                       const float* __restrict__ gm, const float* __restrict__ bt,
                       const float* __restrict__ mn, const float* __restrict__ vr,
                       const float* __restrict__ W1_w, const float* __restrict__ W1_b,
                       const float* __restrict__ W2_w, const float* __restrict__ W2_b) {
    int o = blockIdx.x;
    int t = threadIdx.x;   // 128
    __shared__ float w1r[C_], w2r[C_], ssh[C_], dsh[C_];
    float scc = gm[t] * rsqrtf(vr[t] + 1e-5f);
    float bb  = bt[t] - mn[t] * scc;
    ssh[t] = scc;
    dsh[t] = scc * sp_b[t] + bb;
    w1r[t] = W1_w[o*(2*C_) + t];
    w2r[t] = W2_w[o*(2*C_) + t];
    __syncthreads();
    float a1 = 0.f, a2 = 0.f;
    #pragma unroll 8
    for (int c = 0; c < C_; c++) {
        float spv = ssh[c] * sp_w[c*C_ + t];
        a1 += w1r[c] * spv;
        a2 += w2r[c] * spv;
    }
    g_W1e[o*C_ + t] = a1;
    g_W2e[o*C_ + t] = a2;
    if (t == 0) {
        float s1 = 0.f, s2 = 0.f;
        for (int c = 0; c < C_; c++) { s1 += w1r[c]*dsh[c]; s2 += w2r[c]*dsh[c]; }
        g_b1e[o] = W1_b[o] + s1;
        g_b2e[o] = W2_b[o] + s2;
    }
}

// ---------------- K3: fused graph mix (float4-vectorized, padded rows) ----------
__global__ void k_mix(const float* __restrict__ g1) {
    int bc = blockIdx.x;                // b*C + c
    int b = bc >> 7;
    __shared__ __align__(16) float g1p[T_][28];       // padded rows
    __shared__ __align__(16) float Asp[V_][28];
    __shared__ __align__(16) float Ats[T_*T2_];       // [t][y] rows of 32
    __shared__ __align__(16) float Ms[T_][28];        // [t][u]
    const float* p = g1 + (size_t)bc * (T_*V_);
    int tid = threadIdx.x;
    for (int i = tid; i < T_*28; i += 256) {
        int t = i / 28, v = i % 28;
        g1p[t][v] = (v < V_) ? p[t*V_ + v] : 0.f;
    }
    for (int i = tid; i < V_*28; i += 256) {
        int u = i / 28, v = i % 28;
        Asp[u][v] = (v < V_) ? g_As[(size_t)b*V_*V_ + u*V_ + v] : 0.f;
    }
    for (int i = tid; i < T_*T2_; i += 256) Ats[i] = g_Ate[(size_t)b*T_*T2_ + i];
    __syncthreads();
    // stage 1: Ms[t][u] = sum_v g1p[t][v] * Asp[u][v]
    for (int i = tid; i < T_*V_; i += 256) {
        int t = i / V_, u = i % V_;
        float ax = 0.f, ay = 0.f, az = 0.f, aw = 0.f;
        #pragma unroll
        for (int g = 0; g < 7; g++) {
            float4 x = *(const float4*)&g1p[t][g*4];
            float4 y = *(const float4*)&Asp[u][g*4];
            ax += x.x*y.x; ay += x.y*y.y; az += x.z*y.z; aw += x.w*y.w;
        }
        Ms[t][u] = (ax + ay) + (az + aw);
    }
    __syncthreads();
    // stage 2: out[y][u] = sum_t Ms[t][u] * Ats[t][y]
    if (tid < V_ * 8) {
        int u = tid % V_, y4 = tid / V_;
        float a0 = 0.f, a1 = 0.f, a2 = 0.f, a3 = 0.f;
        #pragma unroll 8
        for (int t = 0; t < T_; t++) {
            float m = Ms[t][u];
            float4 at = *(const float4*)&Ats[t*T2_ + y4*4];
            a0 += m * at.x; a1 += m * at.y; a2 += m * at.z; a3 += m * at.w;
        }
        float* o = g_nu2 + (size_t)bc * COLS + u;
        o[(y4*4 + 0)*V_] = a0;
        o[(y4*4 + 1)*V_] = a1;
        o[(y4*4 + 2)*V_] = a2;
        o[(y4*4 + 3)*V_] = a3;
    }
}

// ---------------- K5: W1/W2 dual GEMM via tf32 mma.sync + gate + BN -> g2 -----
#define KC 32
__global__ __launch_bounds__(256) void k_out(
                      const float* __restrict__ h2,
                      const float* __restrict__ W1_w, const float* __restrict__ W2_w,
                      const float* __restrict__ gm, const float* __restrict__ bt,
                      const float* __restrict__ mn, const float* __restrict__ vr,
                      float* __restrict__ g2) {
    int b  = blockIdx.z;
    int o0 = blockIdx.y * 128;
    int c0 = blockIdx.x * 64;
    __shared__ __align__(16) unsigned W1t[128][36];   // [m][k] pad 36 -> conflict-free frags
    __shared__ __align__(16) unsigned W2t[128][36];
    __shared__ __align__(16) unsigned Xt[KC][72];     // [k][n] pad 72 -> conflict-free frags
    int tid  = threadIdx.x;
    int warp = tid >> 5, lane = tid & 31;
    int wm = warp >> 1, wn = warp & 1;
    int gid = lane >> 2, tig = lane & 3;

    float accA[2][4][4] = {};   // [mt][nt][frag]
    float accG[2][4][4] = {};

    #pragma unroll 1
    for (int half = 0; half < 2; half++) {
        const float* w1src; const float* w2src; int wstride;
        const float* xsrc;
        if (half == 0) {
            w1src = g_W1e + (size_t)o0 * C_;
            w2src = g_W2e + (size_t)o0 * C_;
            wstride = C_;
            xsrc = g_nu2 + (size_t)b * C_ * COLS;
        } else {
            w1src = W1_w + (size_t)o0 * (2*C_) + C_;
            w2src = W2_w + (size_t)o0 * (2*C_) + C_;
            wstride = 2*C_;
            xsrc = h2 + (size_t)b * C_ * COLS;
        }
        #pragma unroll 1
        for (int k0 = 0; k0 < C_; k0 += KC) {
            // load W tiles (128 x 32 each), converted to tf32
            for (int j = tid; j < 1024; j += 256) {
                int oo = j >> 3, kk = (j & 7) * 4;
                float4 w1 = *(const float4*)(w1src + (size_t)oo*wstride + k0 + kk);
                float4 w2 = *(const float4*)(w2src + (size_t)oo*wstride + k0 + kk);
                uint4 u1 = { f2tf32(w1.x), f2tf32(w1.y), f2tf32(w1.z), f2tf32(w1.w) };
                uint4 u2 = { f2tf32(w2.x), f2tf32(w2.y), f2tf32(w2.z), f2tf32(w2.w) };
                *(uint4*)&W1t[oo][kk] = u1;
                *(uint4*)&W2t[oo][kk] = u2;
            }
            // load X tile (32 x 64)
            for (int j = tid; j < 512; j += 256) {
                int kk = j >> 4, cc = (j & 15) * 4;
                int col = c0 + cc;
                float4 x = (col < COLS) ? *(const float4*)(xsrc + (size_t)(k0 + kk)*COLS + col)
                                        : make_float4(0.f, 0.f, 0.f, 0.f);
                uint4 ux = { f2tf32(x.x), f2tf32(x.y), f2tf32(x.z), f2tf32(x.w) };
                *(uint4*)&Xt[kk][cc] = ux;
            }
            __syncthreads();
            #pragma unroll
            for (int ks = 0; ks < KC; ks += 8) {
                unsigned a1[2][4], a2[2][4], bx[4][2];
                #pragma unroll
                for (int mt = 0; mt < 2; mt++) {
                    int row = wm*32 + mt*16;
                    a1[mt][0] = W1t[row + gid    ][ks + tig    ];
                    a1[mt][1] = W1t[row + gid + 8][ks + tig    ];
                    a1[mt][2] = W1t[row + gid    ][ks + tig + 4];
                    a1[mt][3] = W1t[row + gid + 8][ks + tig + 4];
                    a2[mt][0] = W2t[row + gid    ][ks + tig    ];
                    a2[mt][1] = W2t[row + gid + 8][ks + tig    ];
                    a2[mt][2] = W2t[row + gid    ][ks + tig + 4];
                    a2[mt][3] = W2t[row + gid + 8][ks + tig + 4];
                }
                #pragma unroll
                for (int nt = 0; nt < 4; nt++) {
                    int n = wn*32 + nt*8 + gid;
                    bx[nt][0] = Xt[ks + tig    ][n];
                    bx[nt][1] = Xt[ks + tig + 4][n];
                }
                #pragma unroll
                for (int mt = 0; mt < 2; mt++)
                    #pragma unroll
                    for (int nt = 0; nt < 4; nt++) {
                        mma8(accA[mt][nt], a1[mt], bx[nt]);
                        mma8(accG[mt][nt], a2[mt], bx[nt]);
                    }
            }
            __syncthreads();
        }
    }

    // epilogue: bias + gate + BN, float2 stores
    #pragma unroll
    for (int mt = 0; mt < 2; mt++) {
        #pragma unroll
        for (int rh = 0; rh < 2; rh++) {
            int o = o0 + wm*32 + mt*16 + gid + rh*8;
            float sc = gm[o] * rsqrtf(vr[o] + 1e-5f);
            float bb = bt[o] - mn[o]*sc;
            float b1 = g_b1e[o], b2 = g_b2e[o];
            #pragma unroll
            for (int nt = 0; nt < 4; nt++) {
                int col = c0 + wn*32 + nt*8 + tig*2;
                if (col < COLS) {
                    float a0 = accA[mt][nt][rh*2 + 0] + b1;
                    float a1v = accA[mt][nt][rh*2 + 1] + b1;
                    float g0 = accG[mt][nt][rh*2 + 0] + b2;
                    float g1v = accG[mt][nt][rh*2 + 1] + b2;
                    float2 vv;
                    vv.x = (a0  / (1.f + __expf(-g0 ))) * sc + bb;
                    vv.y = (a1v / (1.f + __expf(-g1v))) * sc + bb;
                    *(float2*)&g2[((size_t)(b*O_ + o))*COLS + col] = vv;
                }
            }
        }
    }
}

// ---------------- launch ----------------
extern "C" void kernel_launch(void* const* d_in, const int* in_sizes, int n_in,
                              void* d_out, int out_size) {
    const float* g1    = (const float*)d_in[0];
    const float* h2    = (const float*)d_in[1];
    const float* As_r  = (const float*)d_in[2];
    const float* At_r  = (const float*)d_in[3];
    const float* sc1_w = (const float*)d_in[4];
    const float* sc1_b = (const float*)d_in[5];
    const float* sc2_w = (const float*)d_in[6];
    const float* sc2_b = (const float*)d_in[7];
    const float* tc1_w = (const float*)d_in[8];
    const float* tc1_b = (const float*)d_in[9];
    const float* tc2_w = (const float*)d_in[10];
    const float* tc2_b = (const float*)d_in[11];
    const float* act_s = (const float*)d_in[12];
    const float* act_t = (const float*)d_in[13];
    const float* sp_w  = (const float*)d_in[14];
    const float* sp_b  = (const float*)d_in[15];
    const float* sp_gm = (const float*)d_in[16];
    const float* sp_bt = (const float*)d_in[17];
    const float* sp_mn = (const float*)d_in[18];
    const float* sp_vr = (const float*)d_in[19];
    const float* W1_w  = (const float*)d_in[20];
    const float* W1_b  = (const float*)d_in[21];
    const float* W2_w  = (const float*)d_in[22];
    const float* W2_b  = (const float*)d_in[23];
    const float* bn_gm = (const float*)d_in[24];
    const float* bn_bt = (const float*)d_in[25];
    const float* bn_mn = (const float*)d_in[26];
    const float* bn_vr = (const float*)d_in[27];

    float* out = (float*)d_out;
    float* out_g2     = out;                       // 26,214,400
    float* out_As_at  = out + 26214400;            // 80,000
    float* out_At_at  = out + 26294400;            // 524,288
    float* out_As_act = out + 26818688;            // 80,000
    float* out_At_act = out + 26898688;            // 524,288

    k_reduce<<<B_*C_, 256>>>(g1);
    k_prep<<<O_, 128>>>(sp_w, sp_b, sp_gm, sp_bt, sp_mn, sp_vr,
                        W1_w, W1_b, W2_w, W2_b);
    k_As<<<B_, 256>>>(sc1_w, sc1_b, sc2_w, sc2_b, As_r, act_s, out_As_at, out_As_act);
    k_At<<<B_, 256>>>(tc1_w, tc1_b, tc2_w, tc2_b, At_r, act_t, out_At_at, out_At_act);
    k_mix<<<B_*C_, 256>>>(g1);
    k_out<<<dim3(13, 2, B_), 256>>>(h2, W1_w, W2_w,
                                    bn_gm, bn_bt, bn_mn, bn_vr, out_g2);
}

// round 10
// speedup vs baseline: 3.4771x; 1.4634x over previous
#include <cuda_runtime.h>
#include <cuda_bf16.h>
#include <math.h>

#define B_ 128
#define C_ 128
#define T_ 64
#define V_ 25
#define R_ 16
#define O_ 256
#define T2_ 32
#define COLS 800   // T2_*V_

// ---------------- scratch (device globals; no allocs allowed) ----------------
__device__ float g_sf[B_*V_*C_];          // mean over T   [b][v][c]
__device__ float g_tf[B_*T_*C_];          // mean over V   [b][t][c]
__device__ float g_t1[B_*T_*R_];          // [b][t][r]
__device__ float g_t2[B_*R_*T_];          // [b][r][t]
__device__ float g_s1[B_*V_*R_];          // [b][v][r]
__device__ float g_s2[B_*R_*V_];          // [b][r][v]
__device__ float g_As[B_*V_*V_];          // As = As_at + As_act
__device__ float g_Ate[B_*T_*T2_];        // At[:, ::2]  [b][t][y]
__device__ float g_nu2[B_*C_*COLS];       // after graph mix [b][c][y*25+v]
__device__ float g_Wc1[O_*256];           // combined tf32-rounded weights (k=0..255)
__device__ float g_Wc2[O_*256];
__device__ float g_b1e[O_];
__device__ float g_b2e[O_];

__device__ __forceinline__ unsigned f2tf32(float f) {
    unsigned r; asm("cvt.rna.tf32.f32 %0, %1;" : "=r"(r) : "f"(f)); return r;
}
__device__ __forceinline__ float tf32r(float f) {
    return __uint_as_float(f2tf32(f));
}
__device__ __forceinline__ void mma8(float* d, const unsigned* a, const unsigned* b) {
    asm volatile(
      "mma.sync.aligned.m16n8k8.row.col.f32.tf32.tf32.f32 "
      "{%0,%1,%2,%3},{%4,%5,%6,%7},{%8,%9},{%0,%1,%2,%3};\n"
      : "+f"(d[0]), "+f"(d[1]), "+f"(d[2]), "+f"(d[3])
      : "r"(a[0]), "r"(a[1]), "r"(a[2]), "r"(a[3]), "r"(b[0]), "r"(b[1]));
}
__device__ __forceinline__ void cpa16(unsigned s, const void* g) {
    asm volatile("cp.async.ca.shared.global [%0], [%1], 16;" :: "r"(s), "l"(g));
}
__device__ __forceinline__ void cpa_commit() {
    asm volatile("cp.async.commit_group;");
}
__device__ __forceinline__ void cpa_wait0() {
    asm volatile("cp.async.wait_group 0;");
}

// ---------------- K1: fused means over T and V (transposed outputs) ----------
__global__ void k_reduce(const float* __restrict__ g1) {
    int bc = blockIdx.x;                       // b*C + c
    int b = bc >> 7, c = bc & 127;
    const float* p = g1 + (size_t)bc * (T_*V_);
    __shared__ __align__(16) float s[T_*V_];
    for (int i = threadIdx.x; i < T_*V_; i += blockDim.x) s[i] = p[i];
    __syncthreads();
    int tid = threadIdx.x;
    if (tid < T_) {
        float acc = 0.f;
        #pragma unroll
        for (int v = 0; v < V_; v++) acc += s[tid*V_ + v];
        g_tf[((size_t)b*T_ + tid)*C_ + c] = acc * (1.f/V_);
    } else if (tid < T_ + V_) {
        int v = tid - T_;
        float acc = 0.f;
        #pragma unroll
        for (int t = 0; t < T_; t++) acc += s[t*V_ + v];
        g_sf[((size_t)b*V_ + v)*C_ + c] = acc * (1.f/T_);
    }
}

// ---------------- KA1: rank projections, grid (B,4) -------------------------
// y=0: t1[b][t][r]   y=1: t2[b][r][t]   y=2: s1[b][v][r]   y=3: s2[b][r][v]
__global__ void kA1(const float* __restrict__ tc1_w, const float* __restrict__ tc1_b,
                    const float* __restrict__ tc2_w, const float* __restrict__ tc2_b,
                    const float* __restrict__ sc1_w, const float* __restrict__ sc1_b,
                    const float* __restrict__ sc2_w, const float* __restrict__ sc2_b) {
    int b = blockIdx.x, which = blockIdx.y;
    __shared__ __align__(16) float fs[T_][132];
    __shared__ __align__(16) float ws[R_][132];
    const float* w; const float* bias; const float* feat; int n;
    float* outp; int out_rowmajor;   // rowmajor: [row][r], else [r][row]
    switch (which) {
        case 0: w = tc1_w; bias = tc1_b; feat = g_tf + (size_t)b*T_*C_; n = T_;
                outp = g_t1 + (size_t)b*T_*R_; out_rowmajor = 1; break;
        case 1: w = tc2_w; bias = tc2_b; feat = g_tf + (size_t)b*T_*C_; n = T_;
                outp = g_t2 + (size_t)b*R_*T_; out_rowmajor = 0; break;
        case 2: w = sc1_w; bias = sc1_b; feat = g_sf + (size_t)b*V_*C_; n = V_;
                outp = g_s1 + (size_t)b*V_*R_; out_rowmajor = 1; break;
        default: w = sc2_w; bias = sc2_b; feat = g_sf + (size_t)b*V_*C_; n = V_;
                outp = g_s2 + (size_t)b*R_*V_; out_rowmajor = 0; break;
    }
    int tid = threadIdx.x;    // 128
    for (int i = tid; i < n*C_; i += 128) {
        int row = i >> 7, c = i & 127;
        fs[row][c] = feat[i];
    }
    for (int i = tid; i < R_*C_; i += 128) {
        int r = i >> 7, c = i & 127;
        ws[r][c] = w[i];
    }
    __syncthreads();
    for (int i = tid; i < n*R_; i += 128) {
        int row = i >> 4, r = i & 15;
        float a0 = 0.f, a1 = 0.f, a2 = 0.f, a3 = 0.f;
        #pragma unroll 8
        for (int g = 0; g < 32; g++) {
            float4 f = *(const float4*)&fs[row][g*4];
            float4 x = *(const float4*)&ws[r][g*4];
            a0 += f.x*x.x; a1 += f.y*x.y; a2 += f.z*x.z; a3 += f.w*x.w;
        }
        float res = (a0 + a1) + (a2 + a3) + bias[r];
        if (out_rowmajor) outp[row*R_ + r] = res;
        else              outp[r*n + row] = res;
    }
}

// ---------------- KA2: outer-product + tanh, grid (B,2) ---------------------
__global__ void kA2(const float* __restrict__ As_r, const float* __restrict__ act_s,
                    const float* __restrict__ At_r, const float* __restrict__ act_t,
                    float* __restrict__ out_As_at,  float* __restrict__ out_As_act,
                    float* __restrict__ out_At_at,  float* __restrict__ out_At_act) {
    int b = blockIdx.x;
    int tid = threadIdx.x;    // 256
    if (blockIdx.y == 0) {
        __shared__ __align__(16) float p1[V_][R_];
        __shared__ __align__(16) float p2[R_][V_ + 3];
        for (int i = tid; i < V_*R_; i += 256) p1[i>>4][i&15] = g_s1[(size_t)b*V_*R_ + i];
        for (int i = tid; i < R_*V_; i += 256) p2[i/V_][i%V_] = g_s2[(size_t)b*R_*V_ + i];
        __syncthreads();
        for (int i = tid; i < V_*V_; i += 256) {
            int v = i / V_, u = i % V_;
            float a = 0.f;
            #pragma unroll
            for (int r = 0; r < R_; r++) a += p1[v][r] * p2[r][u];
            float at  = fmaxf(tanhf(a), 0.f);
            float act = As_r[(size_t)b*V_*V_ + i] * act_s[i];
            out_As_at[(size_t)b*V_*V_ + i]  = at;
            out_As_act[(size_t)b*V_*V_ + i] = act;
            g_As[(size_t)b*V_*V_ + i] = at + act;
        }
    } else {
        __shared__ __align__(16) float p1[T_][R_ + 1];
        __shared__ __align__(16) float p2[R_][T_ + 3];
        for (int i = tid; i < T_*R_; i += 256) p1[i>>4][i&15] = g_t1[(size_t)b*T_*R_ + i];
        for (int i = tid; i < R_*T_; i += 256) p2[i>>6][i&63] = g_t2[(size_t)b*R_*T_ + i];
        __syncthreads();
        for (int i = tid; i < T_*T_; i += 256) {
            int t = i >> 6, y = i & 63;
            float a = 0.f;
            #pragma unroll
            for (int r = 0; r < R_; r++) a += p1[t][r] * p2[r][y];
            float at  = fmaxf(tanhf(a), 0.f);
            float act = At_r[(size_t)b*T_*T_ + i] * act_t[i];
            out_At_at[(size_t)b*T_*T_ + i]  = at;
            out_At_act[(size_t)b*T_*T_ + i] = act;
            if ((y & 1) == 0)
                g_Ate[(size_t)b*T_*T2_ + t*T2_ + (y >> 1)] = at + act;
        }
    }
}

// ---------------- K_prep: fold sp+BN into W1/W2, emit combined tf32 weights --
__global__ void k_prep(const float* __restrict__ sp_w, const float* __restrict__ sp_b,
                       const float* __restrict__ gm, const float* __restrict__ bt,
                       const float* __restrict__ mn, const float* __restrict__ vr,
                       const float* __restrict__ W1_w, const float* __restrict__ W1_b,
                       const float* __restrict__ W2_w, const float* __restrict__ W2_b) {
    int o = blockIdx.x;
    int t = threadIdx.x;   // 128
    __shared__ float w1r[C_], w2r[C_], dsh[C_], ssh[C_];
    float scc = gm[t] * rsqrtf(vr[t] + 1e-5f);
    float bb  = bt[t] - mn[t] * scc;
    ssh[t] = scc;
    dsh[t] = scc * sp_b[t] + bb;
    w1r[t] = W1_w[o*(2*C_) + t];
    w2r[t] = W2_w[o*(2*C_) + t];
    __syncthreads();
    float a1 = 0.f, a2 = 0.f;
    #pragma unroll 8
    for (int c = 0; c < C_; c++) {
        float spv = ssh[c] * sp_w[c*C_ + t];
        a1 += w1r[c] * spv;
        a2 += w2r[c] * spv;
    }
    g_Wc1[o*256 + t] = tf32r(a1);
    g_Wc2[o*256 + t] = tf32r(a2);
    g_Wc1[o*256 + 128 + t] = tf32r(W1_w[o*(2*C_) + C_ + t]);
    g_Wc2[o*256 + 128 + t] = tf32r(W2_w[o*(2*C_) + C_ + t]);
    if (t == 0) {
        float s1 = 0.f, s2 = 0.f;
        for (int c = 0; c < C_; c++) { s1 += w1r[c]*dsh[c]; s2 += w2r[c]*dsh[c]; }
        g_b1e[o] = W1_b[o] + s1;
        g_b2e[o] = W2_b[o] + s2;
    }
}

// ---------------- K3: fused graph mix (register-blocked) ----------------------
__global__ void k_mix(const float* __restrict__ g1) {
    int bc = blockIdx.x;                // b*C + c
    int b = bc >> 7;
    __shared__ __align__(16) float g1s[T_][28];
    __shared__ __align__(16) float Asp[V_][28];
    __shared__ __align__(16) float Ats[T_][T2_];
    __shared__ __align__(16) float Mst[V_][68];      // [u][t] transposed, pad 68
    const float* p = g1 + (size_t)bc * (T_*V_);
    int tid = threadIdx.x;
    for (int i = tid; i < T_*28; i += 256) {
        int t = i / 28, v = i % 28;
        g1s[t][v] = (v < V_) ? p[t*V_ + v] : 0.f;
    }
    for (int i = tid; i < V_*28; i += 256) {
        int u = i / 28, v = i % 28;
        Asp[u][v] = (v < V_) ? g_As[(size_t)b*V_*V_ + u*V_ + v] : 0.f;
    }
    for (int i = tid; i < T_*T2_; i += 256) Ats[i >> 5][i & 31] = g_Ate[(size_t)b*T_*T2_ + i];
    __syncthreads();
    // stage 1: Mst[u][t] = sum_v g1s[t][v] * Asp[u][v]; thread = (t, quarter)
    {
        int t = tid >> 2, q = tid & 3;
        int u0 = (q == 0) ? 0 : (6*q + 1);
        int cnt = (q == 0) ? 7 : 6;
        float4 gr[7];
        #pragma unroll
        for (int g = 0; g < 7; g++) gr[g] = *(const float4*)&g1s[t][g*4];
        for (int j = 0; j < cnt; j++) {
            int u = u0 + j;
            float a0 = 0.f, a1 = 0.f, a2 = 0.f, a3 = 0.f;
            #pragma unroll
            for (int g = 0; g < 7; g++) {
                float4 y = *(const float4*)&Asp[u][g*4];
                a0 += gr[g].x*y.x; a1 += gr[g].y*y.y;
                a2 += gr[g].z*y.z; a3 += gr[g].w*y.w;
            }
            Mst[u][t] = (a0 + a1) + (a2 + a3);
        }
    }
    __syncthreads();
    // stage 2: out[y][u] = sum_t Mst[u][t] * Ats[t][y]; thread = (u, y-quad)
    if (tid < V_ * 8) {
        int u = tid % V_, y4 = tid / V_;
        float a0 = 0.f, a1 = 0.f, a2 = 0.f, a3 = 0.f;
        #pragma unroll 4
        for (int t0 = 0; t0 < T_; t0 += 4) {
            float4 ms = *(const float4*)&Mst[u][t0];
            float4 q0 = *(const float4*)&Ats[t0+0][y4*4];
            float4 q1 = *(const float4*)&Ats[t0+1][y4*4];
            float4 q2 = *(const float4*)&Ats[t0+2][y4*4];
            float4 q3 = *(const float4*)&Ats[t0+3][y4*4];
            a0 += ms.x*q0.x + ms.y*q1.x + ms.z*q2.x + ms.w*q3.x;
            a1 += ms.x*q0.y + ms.y*q1.y + ms.z*q2.y + ms.w*q3.y;
            a2 += ms.x*q0.z + ms.y*q1.z + ms.z*q2.z + ms.w*q3.z;
            a3 += ms.x*q0.w + ms.y*q1.w + ms.z*q2.w + ms.w*q3.w;
        }
        float* o = g_nu2 + (size_t)bc * COLS + u;
        o[(y4*4 + 0)*V_] = a0;
        o[(y4*4 + 1)*V_] = a1;
        o[(y4*4 + 2)*V_] = a2;
        o[(y4*4 + 3)*V_] = a3;
    }
}

// ---------------- K5: dual GEMM tf32 mma + cp.async pipeline -> g2 -----------
#define KC 32
#define NCHUNK 8
// dyn smem: W: [2 stg][2 mat][128][36] u32 = 73728B ; X: [2][32][72] u32 = 18432B
#define SMEM_W_ELEMS (2*2*128*36)
#define SMEM_TOTAL_BYTES ((SMEM_W_ELEMS + 2*32*72) * 4)
__global__ __launch_bounds__(256) void k_out(
                      const float* __restrict__ h2,
                      const float* __restrict__ gm, const float* __restrict__ bt,
                      const float* __restrict__ mn, const float* __restrict__ vr,
                      float* __restrict__ g2) {
    extern __shared__ __align__(16) char smem_raw[];
    unsigned* Wb = (unsigned*)smem_raw;                 // [(st*2+mat)*128 + oo]*36 + k
    unsigned* Xb = (unsigned*)smem_raw + SMEM_W_ELEMS;  // [st*32 + row]*72 + cc

    int b  = blockIdx.z;
    int o0 = blockIdx.y * 128;
    int c0 = blockIdx.x * 64;
    int tid  = threadIdx.x;
    int warp = tid >> 5, lane = tid & 31;
    int wm = warp >> 1, wn = warp & 1;
    int gid = lane >> 2, tig = lane & 3;

    const float* xsrc0 = g_nu2 + (size_t)b * C_ * COLS;
    const float* xsrc1 = h2   + (size_t)b * C_ * COLS;

    float accA[2][4][4] = {};
    float accG[2][4][4] = {};

    // W cp.async: 2048 16B chunks per k-chunk -> 8 per thread
    int wj_mat[8], wj_oo[8], wj_kq[8];
    #pragma unroll
    for (int s = 0; s < 8; s++) {
        int j = tid + s*256;
        wj_mat[s] = j >> 10; int rem = j & 1023;
        wj_oo[s] = rem >> 3; wj_kq[s] = rem & 7;
    }
    // X: 512 float4 per chunk -> 2 per thread
    int xr0 = tid >> 4,        xq0 = tid & 15;
    int xr1 = (tid+256) >> 4,  xq1 = (tid+256) & 15;

    auto issueW = [&](int chunk, int st) {
        #pragma unroll
        for (int s = 0; s < 8; s++) {
            const float* src = (wj_mat[s] ? g_Wc2 : g_Wc1)
                             + (size_t)(o0 + wj_oo[s]) * 256 + chunk*KC + wj_kq[s]*4;
            unsigned daddr = (unsigned)__cvta_generic_to_shared(
                Wb + ((size_t)(st*2 + wj_mat[s])*128 + wj_oo[s])*36 + wj_kq[s]*4);
            cpa16(daddr, src);
        }
        cpa_commit();
    };
    auto loadX = [&](int chunk, float4& x0, float4& x1) {
        const float* xs = (chunk < 4) ? xsrc0 : xsrc1;
        int kbase = (chunk < 4) ? chunk*KC : (chunk*KC - 128);
        int col0 = c0 + xq0*4, col1 = c0 + xq1*4;
        x0 = (col0 < COLS) ? *(const float4*)(xs + (size_t)(kbase + xr0)*COLS + col0)
                           : make_float4(0.f,0.f,0.f,0.f);
        x1 = (col1 < COLS) ? *(const float4*)(xs + (size_t)(kbase + xr1)*COLS + col1)
                           : make_float4(0.f,0.f,0.f,0.f);
    };
    auto storeX = [&](int st, const float4& x0, const float4& x1) {
        uint4 u0 = { f2tf32(x0.x), f2tf32(x0.y), f2tf32(x0.z), f2tf32(x0.w) };
        uint4 u1 = { f2tf32(x1.x), f2tf32(x1.y), f2tf32(x1.z), f2tf32(x1.w) };
        *(uint4*)(Xb + (st*32 + xr0)*72 + xq0*4) = u0;
        *(uint4*)(Xb + (st*32 + xr1)*72 + xq1*4) = u1;
    };

    // prologue: chunk 0 -> stage 0
    {
        issueW(0, 0);
        float4 x0, x1; loadX(0, x0, x1); storeX(0, x0, x1);
        cpa_wait0();
        __syncthreads();
    }

    #pragma unroll 1
    for (int c = 0; c < NCHUNK; c++) {
        int cur = c & 1, nxt = cur ^ 1;
        float4 px0, px1;
        if (c < NCHUNK-1) {
            issueW(c+1, nxt);
            loadX(c+1, px0, px1);
        }
        // compute on cur
        const unsigned* W1p = Wb + (size_t)(cur*2 + 0)*128*36;
        const unsigned* W2p = Wb + (size_t)(cur*2 + 1)*128*36;
        const unsigned* Xp  = Xb + (size_t)cur*32*72;
        #pragma unroll
        for (int ks = 0; ks < KC; ks += 8) {
            unsigned a1[2][4], a2[2][4], bx[4][2];
            #pragma unroll
            for (int mt = 0; mt < 2; mt++) {
                int row = wm*32 + mt*16;
                a1[mt][0] = W1p[(row + gid    )*36 + ks + tig    ];
                a1[mt][1] = W1p[(row + gid + 8)*36 + ks + tig    ];
                a1[mt][2] = W1p[(row + gid    )*36 + ks + tig + 4];
                a1[mt][3] = W1p[(row + gid + 8)*36 + ks + tig + 4];
                a2[mt][0] = W2p[(row + gid    )*36 + ks + tig    ];
                a2[mt][1] = W2p[(row + gid + 8)*36 + ks + tig    ];
                a2[mt][2] = W2p[(row + gid    )*36 + ks + tig + 4];
                a2[mt][3] = W2p[(row + gid + 8)*36 + ks + tig + 4];
            }
            #pragma unroll
            for (int nt = 0; nt < 4; nt++) {
                int n = wn*32 + nt*8 + gid;
                bx[nt][0] = Xp[(ks + tig    )*72 + n];
                bx[nt][1] = Xp[(ks + tig + 4)*72 + n];
            }
            #pragma unroll
            for (int mt = 0; mt < 2; mt++)
                #pragma unroll
                for (int nt = 0; nt < 4; nt++) {
                    mma8(accA[mt][nt], a1[mt], bx[nt]);
                    mma8(accG[mt][nt], a2[mt], bx[nt]);
                }
        }
        if (c < NCHUNK-1) {
            storeX(nxt, px0, px1);
            cpa_wait0();
        }
        __syncthreads();
    }

    // epilogue: bias + gate + BN, float2 stores
    #pragma unroll
    for (int mt = 0; mt < 2; mt++) {
        #pragma unroll
        for (int rh = 0; rh < 2; rh++) {
            int o = o0 + wm*32 + mt*16 + gid + rh*8;
            float sc = gm[o] * rsqrtf(vr[o] + 1e-5f);
            float bb = bt[o] - mn[o]*sc;
            float b1 = g_b1e[o], b2 = g_b2e[o];
            #pragma unroll
            for (int nt = 0; nt < 4; nt++) {
                int col = c0 + wn*32 + nt*8 + tig*2;
                if (col < COLS) {
                    float a0 = accA[mt][nt][rh*2 + 0] + b1;
                    float a1v = accA[mt][nt][rh*2 + 1] + b1;
                    float g0 = accG[mt][nt][rh*2 + 0] + b2;
                    float g1v = accG[mt][nt][rh*2 + 1] + b2;
                    float2 vv;
                    vv.x = (a0  / (1.f + __expf(-g0 ))) * sc + bb;
                    vv.y = (a1v / (1.f + __expf(-g1v))) * sc + bb;
                    *(float2*)&g2[((size_t)(b*O_ + o))*COLS + col] = vv;
                }
            }
        }
    }
}

// ---------------- launch ----------------
extern "C" void kernel_launch(void* const* d_in, const int* in_sizes, int n_in,
                              void* d_out, int out_size) {
    const float* g1    = (const float*)d_in[0];
    const float* h2    = (const float*)d_in[1];
    const float* As_r  = (const float*)d_in[2];
    const float* At_r  = (const float*)d_in[3];
    const float* sc1_w = (const float*)d_in[4];
    const float* sc1_b = (const float*)d_in[5];
    const float* sc2_w = (const float*)d_in[6];
    const float* sc2_b = (const float*)d_in[7];
    const float* tc1_w = (const float*)d_in[8];
    const float* tc1_b = (const float*)d_in[9];
    const float* tc2_w = (const float*)d_in[10];
    const float* tc2_b = (const float*)d_in[11];
    const float* act_s = (const float*)d_in[12];
    const float* act_t = (const float*)d_in[13];
    const float* sp_w  = (const float*)d_in[14];
    const float* sp_b  = (const float*)d_in[15];
    const float* sp_gm = (const float*)d_in[16];
    const float* sp_bt = (const float*)d_in[17];
    const float* sp_mn = (const float*)d_in[18];
    const float* sp_vr = (const float*)d_in[19];
    const float* W1_w  = (const float*)d_in[20];
    const float* W1_b  = (const float*)d_in[21];
    const float* W2_w  = (const float*)d_in[22];
    const float* W2_b  = (const float*)d_in[23];
    const float* bn_gm = (const float*)d_in[24];
    const float* bn_bt = (const float*)d_in[25];
    const float* bn_mn = (const float*)d_in[26];
    const float* bn_vr = (const float*)d_in[27];

    float* out = (float*)d_out;
    float* out_g2     = out;                       // 26,214,400
    float* out_As_at  = out + 26214400;            // 80,000
    float* out_At_at  = out + 26294400;            // 524,288
    float* out_As_act = out + 26818688;            // 80,000
    float* out_At_act = out + 26898688;            // 524,288

    cudaFuncSetAttribute(k_out, cudaFuncAttributeMaxDynamicSharedMemorySize,
                         SMEM_TOTAL_BYTES);

    k_reduce<<<B_*C_, 256>>>(g1);
    k_prep<<<O_, 128>>>(sp_w, sp_b, sp_gm, sp_bt, sp_mn, sp_vr,
                        W1_w, W1_b, W2_w, W2_b);
    kA1<<<dim3(B_, 4), 128>>>(tc1_w, tc1_b, tc2_w, tc2_b,
                              sc1_w, sc1_b, sc2_w, sc2_b);
    kA2<<<dim3(B_, 2), 256>>>(As_r, act_s, At_r, act_t,
                              out_As_at, out_As_act, out_At_at, out_At_act);
    k_mix<<<B_*C_, 256>>>(g1);
    k_out<<<dim3(13, 2, B_), 256, SMEM_TOTAL_BYTES>>>(h2,
                                    bn_gm, bn_bt, bn_mn, bn_vr, out_g2);
}

// round 15
// speedup vs baseline: 4.5612x; 1.3118x over previous
#include <cuda_runtime.h>
#include <cuda_bf16.h>
#include <math.h>

#define B_ 128
#define C_ 128
#define T_ 64
#define V_ 25
#define R_ 16
#define O_ 256
#define T2_ 32
#define COLS 800   // T2_*V_

// ---------------- scratch (device globals; no allocs allowed) ----------------
__device__ float g_sf[B_*V_*C_];          // mean over T   [b][v][c]
__device__ float g_tf[B_*T_*C_];          // mean over V   [b][t][c]
__device__ float g_t1[B_*T_*R_];          // [b][t][r]
__device__ float g_t2[B_*R_*T_];          // [b][r][t]
__device__ float g_s1[B_*V_*R_];          // [b][v][r]
__device__ float g_s2[B_*R_*V_];          // [b][r][v]
__device__ float g_As[B_*V_*V_];          // As = As_at + As_act
__device__ float g_Ate[B_*T_*T2_];        // At[:, ::2]  [b][t][y]
__device__ float g_nu2[B_*C_*COLS];       // after graph mix [b][c][y*25+v]
__device__ float g_Wc1[O_*256];           // combined tf32-rounded weights (k=0..255)
__device__ float g_Wc2[O_*256];
__device__ float g_b1e[O_];
__device__ float g_b2e[O_];

__device__ __forceinline__ unsigned f2tf32(float f) {
    unsigned r; asm("cvt.rna.tf32.f32 %0, %1;" : "=r"(r) : "f"(f)); return r;
}
__device__ __forceinline__ float tf32r(float f) {
    return __uint_as_float(f2tf32(f));
}
__device__ __forceinline__ void mma8(float* d, const unsigned* a, const unsigned* b) {
    asm volatile(
      "mma.sync.aligned.m16n8k8.row.col.f32.tf32.tf32.f32 "
      "{%0,%1,%2,%3},{%4,%5,%6,%7},{%8,%9},{%0,%1,%2,%3};\n"
      : "+f"(d[0]), "+f"(d[1]), "+f"(d[2]), "+f"(d[3])
      : "r"(a[0]), "r"(a[1]), "r"(a[2]), "r"(a[3]), "r"(b[0]), "r"(b[1]));
}
__device__ __forceinline__ void cpa16(unsigned s, const void* g) {
    asm volatile("cp.async.ca.shared.global [%0], [%1], 16;" :: "r"(s), "l"(g));
}
__device__ __forceinline__ void cpa_commit() {
    asm volatile("cp.async.commit_group;");
}
__device__ __forceinline__ void cpa_wait0() {
    asm volatile("cp.async.wait_group 0;");
}

// ---------------- K1: fused means over T and V (transposed outputs) ----------
__global__ void k_reduce(const float* __restrict__ g1) {
    int bc = blockIdx.x;                       // b*C + c
    int b = bc >> 7, c = bc & 127;
    const float* p = g1 + (size_t)bc * (T_*V_);
    __shared__ __align__(16) float s[T_*V_];
    for (int i = threadIdx.x; i < T_*V_; i += blockDim.x) s[i] = p[i];
    __syncthreads();
    int tid = threadIdx.x;
    if (tid < T_) {
        float acc = 0.f;
        #pragma unroll
        for (int v = 0; v < V_; v++) acc += s[tid*V_ + v];
        g_tf[((size_t)b*T_ + tid)*C_ + c] = acc * (1.f/V_);
    } else if (tid < T_ + V_) {
        int v = tid - T_;
        float acc = 0.f;
        #pragma unroll
        for (int t = 0; t < T_; t++) acc += s[t*V_ + v];
        g_sf[((size_t)b*V_ + v)*C_ + c] = acc * (1.f/T_);
    }
}

// ---------------- KA1: rank projections, grid (B,4) -------------------------
__global__ void kA1(const float* __restrict__ tc1_w, const float* __restrict__ tc1_b,
                    const float* __restrict__ tc2_w, const float* __restrict__ tc2_b,
                    const float* __restrict__ sc1_w, const float* __restrict__ sc1_b,
                    const float* __restrict__ sc2_w, const float* __restrict__ sc2_b) {
    int b = blockIdx.x, which = blockIdx.y;
    __shared__ __align__(16) float fs[T_][132];
    __shared__ __align__(16) float ws[R_][132];
    const float* w; const float* bias; const float* feat; int n;
    float* outp; int out_rowmajor;
    switch (which) {
        case 0: w = tc1_w; bias = tc1_b; feat = g_tf + (size_t)b*T_*C_; n = T_;
                outp = g_t1 + (size_t)b*T_*R_; out_rowmajor = 1; break;
        case 1: w = tc2_w; bias = tc2_b; feat = g_tf + (size_t)b*T_*C_; n = T_;
                outp = g_t2 + (size_t)b*R_*T_; out_rowmajor = 0; break;
        case 2: w = sc1_w; bias = sc1_b; feat = g_sf + (size_t)b*V_*C_; n = V_;
                outp = g_s1 + (size_t)b*V_*R_; out_rowmajor = 1; break;
        default: w = sc2_w; bias = sc2_b; feat = g_sf + (size_t)b*V_*C_; n = V_;
                outp = g_s2 + (size_t)b*R_*V_; out_rowmajor = 0; break;
    }
    int tid = threadIdx.x;    // 128
    for (int i = tid; i < n*C_; i += 128) {
        int row = i >> 7, c = i & 127;
        fs[row][c] = feat[i];
    }
    for (int i = tid; i < R_*C_; i += 128) {
        int r = i >> 7, c = i & 127;
        ws[r][c] = w[i];
    }
    __syncthreads();
    for (int i = tid; i < n*R_; i += 128) {
        int row = i >> 4, r = i & 15;
        float a0 = 0.f, a1 = 0.f, a2 = 0.f, a3 = 0.f;
        #pragma unroll 8
        for (int g = 0; g < 32; g++) {
            float4 f = *(const float4*)&fs[row][g*4];
            float4 x = *(const float4*)&ws[r][g*4];
            a0 += f.x*x.x; a1 += f.y*x.y; a2 += f.z*x.z; a3 += f.w*x.w;
        }
        float res = (a0 + a1) + (a2 + a3) + bias[r];
        if (out_rowmajor) outp[row*R_ + r] = res;
        else              outp[r*n + row] = res;
    }
}

// ---------------- KA2: outer-product + tanh, grid (B,2) ---------------------
__global__ void kA2(const float* __restrict__ As_r, const float* __restrict__ act_s,
                    const float* __restrict__ At_r, const float* __restrict__ act_t,
                    float* __restrict__ out_As_at,  float* __restrict__ out_As_act,
                    float* __restrict__ out_At_at,  float* __restrict__ out_At_act) {
    int b = blockIdx.x;
    int tid = threadIdx.x;    // 256
    if (blockIdx.y == 0) {
        __shared__ __align__(16) float p1[V_][R_];
        __shared__ __align__(16) float p2[R_][V_ + 3];
        for (int i = tid; i < V_*R_; i += 256) p1[i>>4][i&15] = g_s1[(size_t)b*V_*R_ + i];
        for (int i = tid; i < R_*V_; i += 256) p2[i/V_][i%V_] = g_s2[(size_t)b*R_*V_ + i];
        __syncthreads();
        for (int i = tid; i < V_*V_; i += 256) {
            int v = i / V_, u = i % V_;
            float a = 0.f;
            #pragma unroll
            for (int r = 0; r < R_; r++) a += p1[v][r] * p2[r][u];
            float at  = fmaxf(tanhf(a), 0.f);
            float act = As_r[(size_t)b*V_*V_ + i] * act_s[i];
            out_As_at[(size_t)b*V_*V_ + i]  = at;
            out_As_act[(size_t)b*V_*V_ + i] = act;
            g_As[(size_t)b*V_*V_ + i] = at + act;
        }
    } else {
        __shared__ __align__(16) float p1[T_][R_ + 1];
        __shared__ __align__(16) float p2[R_][T_ + 3];
        for (int i = tid; i < T_*R_; i += 256) p1[i>>4][i&15] = g_t1[(size_t)b*T_*R_ + i];
        for (int i = tid; i < R_*T_; i += 256) p2[i>>6][i&63] = g_t2[(size_t)b*R_*T_ + i];
        __syncthreads();
        for (int i = tid; i < T_*T_; i += 256) {
            int t = i >> 6, y = i & 63;
            float a = 0.f;
            #pragma unroll
            for (int r = 0; r < R_; r++) a += p1[t][r] * p2[r][y];
            float at  = fmaxf(tanhf(a), 0.f);
            float act = At_r[(size_t)b*T_*T_ + i] * act_t[i];
            out_At_at[(size_t)b*T_*T_ + i]  = at;
            out_At_act[(size_t)b*T_*T_ + i] = act;
            if ((y & 1) == 0)
                g_Ate[(size_t)b*T_*T2_ + t*T2_ + (y >> 1)] = at + act;
        }
    }
}

// ---------------- K_prep: fold sp+BN into W1/W2, emit combined tf32 weights --
__global__ void k_prep(const float* __restrict__ sp_w, const float* __restrict__ sp_b,
                       const float* __restrict__ gm, const float* __restrict__ bt,
                       const float* __restrict__ mn, const float* __restrict__ vr,
                       const float* __restrict__ W1_w, const float* __restrict__ W1_b,
                       const float* __restrict__ W2_w, const float* __restrict__ W2_b) {
    int o = blockIdx.x;
    int t = threadIdx.x;   // 128
    __shared__ float w1r[C_], w2r[C_], dsh[C_], ssh[C_];
    float scc = gm[t] * rsqrtf(vr[t] + 1e-5f);
    float bb  = bt[t] - mn[t] * scc;
    ssh[t] = scc;
    dsh[t] = scc * sp_b[t] + bb;
    w1r[t] = W1_w[o*(2*C_) + t];
    w2r[t] = W2_w[o*(2*C_) + t];
    __syncthreads();
    float a1 = 0.f, a2 = 0.f;
    #pragma unroll 8
    for (int c = 0; c < C_; c++) {
        float spv = ssh[c] * sp_w[c*C_ + t];
        a1 += w1r[c] * spv;
        a2 += w2r[c] * spv;
    }
    g_Wc1[o*256 + t] = tf32r(a1);
    g_Wc2[o*256 + t] = tf32r(a2);
    g_Wc1[o*256 + 128 + t] = tf32r(W1_w[o*(2*C_) + C_ + t]);
    g_Wc2[o*256 + 128 + t] = tf32r(W2_w[o*(2*C_) + C_ + t]);
    if (t == 0) {
        float s1 = 0.f, s2 = 0.f;
        for (int c = 0; c < C_; c++) { s1 += w1r[c]*dsh[c]; s2 += w2r[c]*dsh[c]; }
        g_b1e[o] = W1_b[o] + s1;
        g_b2e[o] = W2_b[o] + s2;
    }
}

// ---------------- K3: graph mix on tensor cores ------------------------------
// nu2[c] = (At_e^T (32x64) @ g1[c] (64x25pad32)) @ As^T  via two tf32 GEMMs.
// Block = (b, group of 8 c); one warp per c.
// dyn smem (floats): g1s[8][64][32]=16384 | AtT[32][68]=2176 | Ass[32][33]=1056 | P[8][32][34]=8704
#define MIX_G1S   0
#define MIX_ATT   (8*64*32)
#define MIX_ASS   (MIX_ATT + 32*68)
#define MIX_P     (MIX_ASS + 32*33)
#define MIX_FLTS  (MIX_P + 8*32*34)
#define MIX_SMEM_BYTES (MIX_FLTS*4)
__global__ __launch_bounds__(256) void k_mix_tc(const float* __restrict__ g1) {
    extern __shared__ __align__(16) float sm[];
    float* g1s = sm + MIX_G1S;     // [c][t][32]
    float* AtT = sm + MIX_ATT;     // [y][68]
    float* Ass = sm + MIX_ASS;     // [u][33]
    float* Pb  = sm + MIX_P;       // [warp][32][34]
    int b = blockIdx.x, c0 = blockIdx.y * 8;
    int tid = threadIdx.x;

    for (int i = tid; i < 32*33; i += 256) Ass[i] = 0.f;
    __syncthreads();
    for (int i = tid; i < V_*V_; i += 256) {
        int u = i / V_, v = i % V_;
        Ass[u*33 + v] = tf32r(g_As[(size_t)b*V_*V_ + i]);
    }
    for (int i = tid; i < T_*T2_; i += 256) {
        int t = i >> 5, y = i & 31;
        AtT[y*68 + t] = tf32r(g_Ate[(size_t)b*T_*T2_ + i]);
    }
    const float* gp = g1 + ((size_t)b*C_ + c0)*(T_*V_);
    for (int i = tid; i < 8*T_*V_; i += 256) {
        int c = i / (T_*V_); int r = i % (T_*V_);
        int t = r / V_, v = r % V_;
        g1s[(c*T_ + t)*32 + v] = tf32r(gp[i]);
    }
    for (int i = tid; i < 8*T_*7; i += 256) {
        int c = i / (T_*7); int r = i % (T_*7);
        int t = r / 7, v = 25 + r % 7;
        g1s[(c*T_ + t)*32 + v] = 0.f;
    }
    __syncthreads();

    int warp = tid >> 5, lane = tid & 31;
    int gid = lane >> 2, tig = lane & 3;
    const float* G = g1s + warp*T_*32;
    float* P = Pb + warp*32*34;

    // GEMM1: P[y][v] = sum_t AtT[y][t] * G[t][v]  (M32 N32 K64)
    float acc[2][4][4] = {};
    #pragma unroll
    for (int ks = 0; ks < 64; ks += 8) {
        unsigned a[2][4], bf[4][2];
        #pragma unroll
        for (int mt = 0; mt < 2; mt++) {
            int y = mt*16;
            a[mt][0] = __float_as_uint(AtT[(y+gid  )*68 + ks+tig  ]);
            a[mt][1] = __float_as_uint(AtT[(y+gid+8)*68 + ks+tig  ]);
            a[mt][2] = __float_as_uint(AtT[(y+gid  )*68 + ks+tig+4]);
            a[mt][3] = __float_as_uint(AtT[(y+gid+8)*68 + ks+tig+4]);
        }
        #pragma unroll
        for (int nt = 0; nt < 4; nt++) {
            int n = nt*8 + gid;
            bf[nt][0] = __float_as_uint(G[(ks+tig  )*32 + n]);
            bf[nt][1] = __float_as_uint(G[(ks+tig+4)*32 + n]);
        }
        #pragma unroll
        for (int mt = 0; mt < 2; mt++)
            #pragma unroll
            for (int nt = 0; nt < 4; nt++)
                mma8(acc[mt][nt], a[mt], bf[nt]);
    }
    // store P (tf32-rounded)
    #pragma unroll
    for (int mt = 0; mt < 2; mt++)
        #pragma unroll
        for (int nt = 0; nt < 4; nt++) {
            int y0 = mt*16 + gid, n0 = nt*8 + 2*tig;
            P[ y0     *34 + n0    ] = tf32r(acc[mt][nt][0]);
            P[ y0     *34 + n0 + 1] = tf32r(acc[mt][nt][1]);
            P[(y0 + 8)*34 + n0    ] = tf32r(acc[mt][nt][2]);
            P[(y0 + 8)*34 + n0 + 1] = tf32r(acc[mt][nt][3]);
        }
    __syncwarp();

    // GEMM2: out[y][u] = sum_v P[y][v] * Ass[u][v]  (M32 N32 K32)
    float acc2[2][4][4] = {};
    #pragma unroll
    for (int ks = 0; ks < 32; ks += 8) {
        unsigned a[2][4], bf[4][2];
        #pragma unroll
        for (int mt = 0; mt < 2; mt++) {
            int y = mt*16;
            a[mt][0] = __float_as_uint(P[(y+gid  )*34 + ks+tig  ]);
            a[mt][1] = __float_as_uint(P[(y+gid+8)*34 + ks+tig  ]);
            a[mt][2] = __float_as_uint(P[(y+gid  )*34 + ks+tig+4]);
            a[mt][3] = __float_as_uint(P[(y+gid+8)*34 + ks+tig+4]);
        }
        #pragma unroll
        for (int nt = 0; nt < 4; nt++) {
            int n = nt*8 + gid;
            bf[nt][0] = __float_as_uint(Ass[n*33 + ks+tig  ]);
            bf[nt][1] = __float_as_uint(Ass[n*33 + ks+tig+4]);
        }
        #pragma unroll
        for (int mt = 0; mt < 2; mt++)
            #pragma unroll
            for (int nt = 0; nt < 4; nt++)
                mma8(acc2[mt][nt], a[mt], bf[nt]);
    }

    float* o = g_nu2 + ((size_t)(b*C_ + c0 + warp))*COLS;
    #pragma unroll
    for (int mt = 0; mt < 2; mt++)
        #pragma unroll
        for (int nt = 0; nt < 4; nt++) {
            int y0 = mt*16 + gid, u0 = nt*8 + 2*tig;
            if (u0 < V_)     o[ y0     *V_ + u0    ] = acc2[mt][nt][0];
            if (u0 + 1 < V_) o[ y0     *V_ + u0 + 1] = acc2[mt][nt][1];
            if (u0 < V_)     o[(y0 + 8)*V_ + u0    ] = acc2[mt][nt][2];
            if (u0 + 1 < V_) o[(y0 + 8)*V_ + u0 + 1] = acc2[mt][nt][3];
        }
}

// ---------------- K5: dual GEMM tf32 mma + cp.async pipeline -> g2 -----------
#define KC 32
#define NCHUNK 8
#define SMEM_W_ELEMS (2*2*128*36)
#define SMEM_TOTAL_BYTES ((SMEM_W_ELEMS + 2*32*72) * 4)
__global__ __launch_bounds__(256) void k_out(
                      const float* __restrict__ h2,
                      const float* __restrict__ gm, const float* __restrict__ bt,
                      const float* __restrict__ mn, const float* __restrict__ vr,
                      float* __restrict__ g2) {
    extern __shared__ __align__(16) char smem_raw[];
    unsigned* Wb = (unsigned*)smem_raw;
    unsigned* Xb = (unsigned*)smem_raw + SMEM_W_ELEMS;

    int b  = blockIdx.z;
    int o0 = blockIdx.y * 128;
    int c0 = blockIdx.x * 64;
    int tid  = threadIdx.x;
    int warp = tid >> 5, lane = tid & 31;
    int wm = warp >> 1, wn = warp & 1;
    int gid = lane >> 2, tig = lane & 3;

    const float* xsrc0 = g_nu2 + (size_t)b * C_ * COLS;
    const float* xsrc1 = h2   + (size_t)b * C_ * COLS;

    float accA[2][4][4] = {};
    float accG[2][4][4] = {};

    int wj_mat[8], wj_oo[8], wj_kq[8];
    #pragma unroll
    for (int s = 0; s < 8; s++) {
        int j = tid + s*256;
        wj_mat[s] = j >> 10; int rem = j & 1023;
        wj_oo[s] = rem >> 3; wj_kq[s] = rem & 7;
    }
    int xr0 = tid >> 4,        xq0 = tid & 15;
    int xr1 = (tid+256) >> 4,  xq1 = (tid+256) & 15;

    auto issueW = [&](int chunk, int st) {
        #pragma unroll
        for (int s = 0; s < 8; s++) {
            const float* src = (wj_mat[s] ? g_Wc2 : g_Wc1)
                             + (size_t)(o0 + wj_oo[s]) * 256 + chunk*KC + wj_kq[s]*4;
            unsigned daddr = (unsigned)__cvta_generic_to_shared(
                Wb + ((size_t)(st*2 + wj_mat[s])*128 + wj_oo[s])*36 + wj_kq[s]*4);
            cpa16(daddr, src);
        }
        cpa_commit();
    };
    auto loadX = [&](int chunk, float4& x0, float4& x1) {
        const float* xs = (chunk < 4) ? xsrc0 : xsrc1;
        int kbase = (chunk < 4) ? chunk*KC : (chunk*KC - 128);
        int col0 = c0 + xq0*4, col1 = c0 + xq1*4;
        x0 = (col0 < COLS) ? *(const float4*)(xs + (size_t)(kbase + xr0)*COLS + col0)
                           : make_float4(0.f,0.f,0.f,0.f);
        x1 = (col1 < COLS) ? *(const float4*)(xs + (size_t)(kbase + xr1)*COLS + col1)
                           : make_float4(0.f,0.f,0.f,0.f);
    };
    auto storeX = [&](int st, const float4& x0, const float4& x1) {
        uint4 u0 = { f2tf32(x0.x), f2tf32(x0.y), f2tf32(x0.z), f2tf32(x0.w) };
        uint4 u1 = { f2tf32(x1.x), f2tf32(x1.y), f2tf32(x1.z), f2tf32(x1.w) };
        *(uint4*)(Xb + (st*32 + xr0)*72 + xq0*4) = u0;
        *(uint4*)(Xb + (st*32 + xr1)*72 + xq1*4) = u1;
    };

    {
        issueW(0, 0);
        float4 x0, x1; loadX(0, x0, x1); storeX(0, x0, x1);
        cpa_wait0();
        __syncthreads();
    }

    #pragma unroll 1
    for (int c = 0; c < NCHUNK; c++) {
        int cur = c & 1, nxt = cur ^ 1;
        float4 px0, px1;
        if (c < NCHUNK-1) {
            issueW(c+1, nxt);
            loadX(c+1, px0, px1);
        }
        const unsigned* W1p = Wb + (size_t)(cur*2 + 0)*128*36;
        const unsigned* W2p = Wb + (size_t)(cur*2 + 1)*128*36;
        const unsigned* Xp  = Xb + (size_t)cur*32*72;
        #pragma unroll
        for (int ks = 0; ks < KC; ks += 8) {
            unsigned a1[2][4], a2[2][4], bx[4][2];
            #pragma unroll
            for (int mt = 0; mt < 2; mt++) {
                int row = wm*32 + mt*16;
                a1[mt][0] = W1p[(row + gid    )*36 + ks + tig    ];
                a1[mt][1] = W1p[(row + gid + 8)*36 + ks + tig    ];
                a1[mt][2] = W1p[(row + gid    )*36 + ks + tig + 4];
                a1[mt][3] = W1p[(row + gid + 8)*36 + ks + tig + 4];
                a2[mt][0] = W2p[(row + gid    )*36 + ks + tig    ];
                a2[mt][1] = W2p[(row + gid + 8)*36 + ks + tig    ];
                a2[mt][2] = W2p[(row + gid    )*36 + ks + tig + 4];
                a2[mt][3] = W2p[(row + gid + 8)*36 + ks + tig + 4];
            }
            #pragma unroll
            for (int nt = 0; nt < 4; nt++) {
                int n = wn*32 + nt*8 + gid;
                bx[nt][0] = Xp[(ks + tig    )*72 + n];
                bx[nt][1] = Xp[(ks + tig + 4)*72 + n];
            }
            #pragma unroll
            for (int mt = 0; mt < 2; mt++)
                #pragma unroll
                for (int nt = 0; nt < 4; nt++) {
                    mma8(accA[mt][nt], a1[mt], bx[nt]);
                    mma8(accG[mt][nt], a2[mt], bx[nt]);
                }
        }
        if (c < NCHUNK-1) {
            storeX(nxt, px0, px1);
            cpa_wait0();
        }
        __syncthreads();
    }

    #pragma unroll
    for (int mt = 0; mt < 2; mt++) {
        #pragma unroll
        for (int rh = 0; rh < 2; rh++) {
            int o = o0 + wm*32 + mt*16 + gid + rh*8;
            float sc = gm[o] * rsqrtf(vr[o] + 1e-5f);
            float bb = bt[o] - mn[o]*sc;
            float b1 = g_b1e[o], b2 = g_b2e[o];
            #pragma unroll
            for (int nt = 0; nt < 4; nt++) {
                int col = c0 + wn*32 + nt*8 + tig*2;
                if (col < COLS) {
                    float a0 = accA[mt][nt][rh*2 + 0] + b1;
                    float a1v = accA[mt][nt][rh*2 + 1] + b1;
                    float g0 = accG[mt][nt][rh*2 + 0] + b2;
                    float g1v = accG[mt][nt][rh*2 + 1] + b2;
                    float2 vv;
                    vv.x = (a0  / (1.f + __expf(-g0 ))) * sc + bb;
                    vv.y = (a1v / (1.f + __expf(-g1v))) * sc + bb;
                    *(float2*)&g2[((size_t)(b*O_ + o))*COLS + col] = vv;
                }
            }
        }
    }
}

// ---------------- launch ----------------
extern "C" void kernel_launch(void* const* d_in, const int* in_sizes, int n_in,
                              void* d_out, int out_size) {
    const float* g1    = (const float*)d_in[0];
    const float* h2    = (const float*)d_in[1];
    const float* As_r  = (const float*)d_in[2];
    const float* At_r  = (const float*)d_in[3];
    const float* sc1_w = (const float*)d_in[4];
    const float* sc1_b = (const float*)d_in[5];
    const float* sc2_w = (const float*)d_in[6];
    const float* sc2_b = (const float*)d_in[7];
    const float* tc1_w = (const float*)d_in[8];
    const float* tc1_b = (const float*)d_in[9];
    const float* tc2_w = (const float*)d_in[10];
    const float* tc2_b = (const float*)d_in[11];
    const float* act_s = (const float*)d_in[12];
    const float* act_t = (const float*)d_in[13];
    const float* sp_w  = (const float*)d_in[14];
    const float* sp_b  = (const float*)d_in[15];
    const float* sp_gm = (const float*)d_in[16];
    const float* sp_bt = (const float*)d_in[17];
    const float* sp_mn = (const float*)d_in[18];
    const float* sp_vr = (const float*)d_in[19];
    const float* W1_w  = (const float*)d_in[20];
    const float* W1_b  = (const float*)d_in[21];
    const float* W2_w  = (const float*)d_in[22];
    const float* W2_b  = (const float*)d_in[23];
    const float* bn_gm = (const float*)d_in[24];
    const float* bn_bt = (const float*)d_in[25];
    const float* bn_mn = (const float*)d_in[26];
    const float* bn_vr = (const float*)d_in[27];

    float* out = (float*)d_out;
    float* out_g2     = out;                       // 26,214,400
    float* out_As_at  = out + 26214400;            // 80,000
    float* out_At_at  = out + 26294400;            // 524,288
    float* out_As_act = out + 26818688;            // 80,000
    float* out_At_act = out + 26898688;            // 524,288

    cudaFuncSetAttribute(k_out, cudaFuncAttributeMaxDynamicSharedMemorySize,
                         SMEM_TOTAL_BYTES);
    cudaFuncSetAttribute(k_mix_tc, cudaFuncAttributeMaxDynamicSharedMemorySize,
                         MIX_SMEM_BYTES);

    k_reduce<<<B_*C_, 256>>>(g1);
    k_prep<<<O_, 128>>>(sp_w, sp_b, sp_gm, sp_bt, sp_mn, sp_vr,
                        W1_w, W1_b, W2_w, W2_b);
    kA1<<<dim3(B_, 4), 128>>>(tc1_w, tc1_b, tc2_w, tc2_b,
                              sc1_w, sc1_b, sc2_w, sc2_b);
    kA2<<<dim3(B_, 2), 256>>>(As_r, act_s, At_r, act_t,
                              out_As_at, out_As_act, out_At_at, out_At_act);
    k_mix_tc<<<dim3(B_, 16), 256, MIX_SMEM_BYTES>>>(g1);
    k_out<<<dim3(13, 2, B_), 256, SMEM_TOTAL_BYTES>>>(h2,
                                    bn_gm, bn_bt, bn_mn, bn_vr, out_g2);
}